// round 10
// baseline (speedup 1.0000x reference)
#include <cuda_runtime.h>
#include <cuda_fp16.h>
#include <math.h>
#include <stdint.h>

#define NROWS 8192
#define EMB   512
#define DFF   2048

// ---------------- scratch (static device globals; no allocs) ----------------
static __device__ __half g_normx[NROWS * EMB];                 // 8 MB
static __device__ __half g_normxT[EMB * NROWS];                // 8 MB
static __device__ __half g_Sh[(size_t)NROWS * NROWS];          // 128 MB (scores/attn, half)
static __device__ float  g_x2[NROWS * EMB];                    // 16 MB
static __device__ __half g_h[NROWS * EMB];                     // 8 MB
static __device__ __half g_t[NROWS * DFF];                     // 32 MB
static __device__ __half g_W1T[(size_t)DFF * EMB];             // 2 MB
static __device__ __half g_W2T[(size_t)EMB * DFF];             // 2 MB

// ---------------- helpers ----------------
__device__ __forceinline__ uint32_t smem_u32(const void* p) {
    uint32_t a;
    asm("{ .reg .u64 t; cvta.to.shared.u64 t, %1; cvt.u32.u64 %0, t; }" : "=r"(a) : "l"(p));
    return a;
}
__device__ __forceinline__ void cp16(uint32_t dst, const void* src) {
    asm volatile("cp.async.cg.shared.global [%0], [%1], 16;" :: "r"(dst), "l"(src));
}
__device__ __forceinline__ void ldsm_x4(uint32_t a[4], uint32_t addr) {
    asm volatile("ldmatrix.sync.aligned.m8n8.x4.shared.b16 {%0,%1,%2,%3}, [%4];"
                 : "=r"(a[0]), "=r"(a[1]), "=r"(a[2]), "=r"(a[3]) : "r"(addr));
}
__device__ __forceinline__ void mma_f16(float c[4], const uint32_t a[4], uint32_t b0, uint32_t b1) {
    asm volatile(
        "mma.sync.aligned.m16n8k16.row.col.f32.f16.f16.f32 "
        "{%0,%1,%2,%3}, {%4,%5,%6,%7}, {%8,%9}, {%0,%1,%2,%3};"
        : "+f"(c[0]), "+f"(c[1]), "+f"(c[2]), "+f"(c[3])
        : "r"(a[0]), "r"(a[1]), "r"(a[2]), "r"(a[3]), "r"(b0), "r"(b1));
}

// ---------------------------------------------------------------------------
// LayerNorm: one block per row, 128 threads. fp32 in, half out.
// ---------------------------------------------------------------------------
__global__ void layernorm_kernel(const float* __restrict__ x,
                                 const float* __restrict__ g,
                                 const float* __restrict__ b,
                                 __half* __restrict__ out) {
    const int row = blockIdx.x;
    const int t = threadIdx.x;
    float4 v = reinterpret_cast<const float4*>(x + (size_t)row * EMB)[t];

    float s  = v.x + v.y + v.z + v.w;
    float ss = v.x * v.x + v.y * v.y + v.z * v.z + v.w * v.w;

    __shared__ float red_s[4], red_ss[4];
    #pragma unroll
    for (int o = 16; o; o >>= 1) {
        s  += __shfl_xor_sync(0xffffffffu, s,  o);
        ss += __shfl_xor_sync(0xffffffffu, ss, o);
    }
    if ((t & 31) == 0) { red_s[t >> 5] = s; red_ss[t >> 5] = ss; }
    __syncthreads();
    s  = red_s[0]  + red_s[1]  + red_s[2]  + red_s[3];
    ss = red_ss[0] + red_ss[1] + red_ss[2] + red_ss[3];

    const float mu  = s * (1.0f / EMB);
    const float var = ss * (1.0f / EMB) - mu * mu;
    const float r   = rsqrtf(var + 1e-5f);

    float4 gv = reinterpret_cast<const float4*>(g)[t];
    float4 bv = reinterpret_cast<const float4*>(b)[t];
    __half2 h0 = __floats2half2_rn((v.x - mu) * r * gv.x + bv.x,
                                   (v.y - mu) * r * gv.y + bv.y);
    __half2 h1 = __floats2half2_rn((v.z - mu) * r * gv.z + bv.z,
                                   (v.w - mu) * r * gv.w + bv.w);
    reinterpret_cast<__half2*>(out + (size_t)row * EMB)[2 * t]     = h0;
    reinterpret_cast<__half2*>(out + (size_t)row * EMB)[2 * t + 1] = h1;
}

// ---------------------------------------------------------------------------
// Row softmax over 8192 cols, half in / half out (in place).
// ---------------------------------------------------------------------------
__global__ void softmax_kernel(__half* __restrict__ S) {
    const size_t row = blockIdx.x;
    __half2* r2 = reinterpret_cast<__half2*>(S + row * (size_t)NROWS);
    const int t = threadIdx.x;

    float v[32];
    float m = -INFINITY;
    #pragma unroll
    for (int i = 0; i < 16; i++) {
        float2 p = __half22float2(r2[t + i * 256]);
        v[2 * i] = p.x; v[2 * i + 1] = p.y;
        m = fmaxf(m, fmaxf(p.x, p.y));
    }

    __shared__ float sm[8];
    #pragma unroll
    for (int o = 16; o; o >>= 1) m = fmaxf(m, __shfl_xor_sync(0xffffffffu, m, o));
    if ((t & 31) == 0) sm[t >> 5] = m;
    __syncthreads();
    m = sm[0];
    #pragma unroll
    for (int i = 1; i < 8; i++) m = fmaxf(m, sm[i]);
    __syncthreads();

    float sum = 0.f;
    #pragma unroll
    for (int i = 0; i < 32; i++) { v[i] = __expf(v[i] - m); sum += v[i]; }
    #pragma unroll
    for (int o = 16; o; o >>= 1) sum += __shfl_xor_sync(0xffffffffu, sum, o);
    if ((t & 31) == 0) sm[t >> 5] = sum;
    __syncthreads();
    sum = sm[0];
    #pragma unroll
    for (int i = 1; i < 8; i++) sum += sm[i];

    const float inv = 1.0f / sum;
    #pragma unroll
    for (int i = 0; i < 16; i++)
        r2[t + i * 256] = __floats2half2_rn(v[2 * i] * inv, v[2 * i + 1] * inv);
}

// ---------------------------------------------------------------------------
// Transposes: out[Cc][R] = in[R][Cc]
// ---------------------------------------------------------------------------
__global__ void transpose_f2h_kernel(const float* __restrict__ in, __half* __restrict__ out,
                                     int R, int Cc) {
    __shared__ float tile[32][34];
    const int bx = blockIdx.x * 32, by = blockIdx.y * 32;
    int x = bx + threadIdx.x;
    #pragma unroll
    for (int i = 0; i < 32; i += 8)
        tile[threadIdx.y + i][threadIdx.x] = in[(size_t)(by + threadIdx.y + i) * Cc + x];
    __syncthreads();
    x = by + threadIdx.x;
    #pragma unroll
    for (int i = 0; i < 32; i += 8)
        out[(size_t)(bx + threadIdx.y + i) * R + x] = __float2half(tile[threadIdx.x][threadIdx.y + i]);
}
__global__ void transpose_h2h_kernel(const __half* __restrict__ in, __half* __restrict__ out,
                                     int R, int Cc) {
    __shared__ __half tile[32][34];
    const int bx = blockIdx.x * 32, by = blockIdx.y * 32;
    int x = bx + threadIdx.x;
    #pragma unroll
    for (int i = 0; i < 32; i += 8)
        tile[threadIdx.y + i][threadIdx.x] = in[(size_t)(by + threadIdx.y + i) * Cc + x];
    __syncthreads();
    x = by + threadIdx.x;
    #pragma unroll
    for (int i = 0; i < 32; i += 8)
        out[(size_t)(bx + threadIdx.y + i) * R + x] = tile[threadIdx.x][threadIdx.y + i];
}

// ---------------------------------------------------------------------------
// fp16 mma.sync GEMM:  D[M,Nn] = A[M,K] * B[Nn,K]^T  (A, B half, K-major).
// CTA 256x128, 8 warps arranged 4(m) x 2(n) -> warp tile 64x64.
// K-chunk 64, 3-stage cp.async pipeline (one barrier per chunk),
// XOR-swizzled smem, ldmatrix.x4 for A and B.
// MODE 0: C = half(acc*scale + aux)     MODE 1: C = acc + aux (f32)
// MODE 2: C = half(relu(acc + bias))    MODE 3: C = acc + bias + aux (f32)
// ---------------------------------------------------------------------------
template <int MODE>
__global__ __launch_bounds__(256, 1)
void mma_gemm(const __half* __restrict__ A, const __half* __restrict__ B,
              void* __restrict__ Cv, int M, int Nn, int K,
              const float* __restrict__ aux, const float* __restrict__ bias,
              float scale) {
    extern __shared__ char smem[];
    const uint32_t sA = smem_u32(smem);            // 3 x 32 KB  (256 rows x 128B)
    const uint32_t sB = sA + 3u * 32768u;          // 3 x 16 KB  (128 rows x 128B)

    const int tid  = threadIdx.x;
    const int lane = tid & 31, wid = tid >> 5;
    const int wm = wid >> 1, wn = wid & 1;         // 4 x 2 warp grid
    const int bm = blockIdx.y * 256, bn = blockIdx.x * 128;
    const int q  = lane & 3, gr = lane >> 2;

    float acc[4][8][4];
    #pragma unroll
    for (int i = 0; i < 4; i++)
        #pragma unroll
        for (int j = 0; j < 8; j++)
            #pragma unroll
            for (int c = 0; c < 4; c++) acc[i][j][c] = 0.f;

    const int a_row_in = ((lane >> 3) & 1) * 8 + (lane & 7);
    const int a_gsel   = lane >> 4;                 // 0 or 1 (k half)
    const int b_nt_ofs = (lane >> 4);               // 0 or 1
    const int b_kh     = (lane >> 3) & 1;
    const int b_row_in = lane & 7;

    auto load_chunk = [&](int k0, int stg) {        // k0 in halfs, chunk = 64
        #pragma unroll
        for (int i = 0; i < 8; i++) {               // A: 256 rows x 8 groups
            int idx = tid + i * 256;
            int r = idx >> 3, cg = idx & 7;
            uint32_t off = (uint32_t)(r * 128 + ((cg ^ (r & 7)) << 4));
            cp16(sA + (uint32_t)stg * 32768u + off,
                 A + (size_t)(bm + r) * K + k0 + cg * 8);
        }
        #pragma unroll
        for (int i = 0; i < 4; i++) {               // B: 128 rows x 8 groups
            int idx = tid + i * 256;
            int r = idx >> 3, cg = idx & 7;
            uint32_t off = (uint32_t)(r * 128 + ((cg ^ (r & 7)) << 4));
            cp16(sB + (uint32_t)stg * 16384u + off,
                 B + (size_t)(bn + r) * K + k0 + cg * 8);
        }
        asm volatile("cp.async.commit_group;");
    };

    const int nk = K / 64;
    load_chunk(0, 0);
    load_chunk(64, 1);

    for (int kc = 0; kc < nk; kc++) {
        if (kc == nk - 1) asm volatile("cp.async.wait_group %0;" :: "n"(0));
        else              asm volatile("cp.async.wait_group %0;" :: "n"(1));
        __syncthreads();

        const int stg = kc % 3;
        const uint32_t aB = sA + (uint32_t)stg * 32768u;
        const uint32_t bB = sB + (uint32_t)stg * 16384u;

        #pragma unroll
        for (int ks = 0; ks < 4; ks++) {
            uint32_t a[4][4];
            #pragma unroll
            for (int mt = 0; mt < 4; mt++) {
                const int row = wm * 64 + mt * 16 + a_row_in;
                const uint32_t g = (uint32_t)((2 * ks + a_gsel) ^ (row & 7));
                ldsm_x4(a[mt], aB + (uint32_t)(row * 128) + (g << 4));
            }
            #pragma unroll
            for (int p = 0; p < 4; p++) {
                uint32_t bfr[4];
                const int n = wn * 64 + (2 * p + b_nt_ofs) * 8 + b_row_in;
                const uint32_t g = (uint32_t)((2 * ks + b_kh) ^ (n & 7));
                ldsm_x4(bfr, bB + (uint32_t)(n * 128) + (g << 4));
                #pragma unroll
                for (int mt = 0; mt < 4; mt++) {
                    mma_f16(acc[mt][2 * p],     a[mt], bfr[0], bfr[1]);
                    mma_f16(acc[mt][2 * p + 1], a[mt], bfr[2], bfr[3]);
                }
            }
        }

        if (kc + 2 < nk) load_chunk((kc + 2) * 64, (kc + 2) % 3);
    }

    // ---------------- epilogue ----------------
    #pragma unroll
    for (int mt = 0; mt < 4; mt++) {
        #pragma unroll
        for (int half_ = 0; half_ < 2; half_++) {
            const int r = bm + wm * 64 + mt * 16 + gr + half_ * 8;
            const size_t ro = (size_t)r * Nn;
            #pragma unroll
            for (int nt = 0; nt < 8; nt++) {
                const int c0 = bn + wn * 64 + nt * 8 + 2 * q;
                float v0 = acc[mt][nt][2 * half_ + 0];
                float v1 = acc[mt][nt][2 * half_ + 1];
                if (MODE == 0) {
                    float2 a2 = *reinterpret_cast<const float2*>(aux + ro + c0);
                    *reinterpret_cast<__half2*>((__half*)Cv + ro + c0) =
                        __floats2half2_rn(v0 * scale + a2.x, v1 * scale + a2.y);
                } else if (MODE == 1) {
                    float2 a2 = *reinterpret_cast<const float2*>(aux + ro + c0);
                    *reinterpret_cast<float2*>((float*)Cv + ro + c0) =
                        make_float2(v0 + a2.x, v1 + a2.y);
                } else if (MODE == 2) {
                    float2 b2 = *reinterpret_cast<const float2*>(bias + c0);
                    *reinterpret_cast<__half2*>((__half*)Cv + ro + c0) =
                        __floats2half2_rn(fmaxf(v0 + b2.x, 0.f), fmaxf(v1 + b2.y, 0.f));
                } else {
                    float2 a2 = *reinterpret_cast<const float2*>(aux + ro + c0);
                    float2 b2 = *reinterpret_cast<const float2*>(bias + c0);
                    *reinterpret_cast<float2*>((float*)Cv + ro + c0) =
                        make_float2(v0 + b2.x + a2.x, v1 + b2.y + a2.y);
                }
            }
        }
    }
}

// ---------------------------------------------------------------------------
extern "C" void kernel_launch(void* const* d_in, const int* in_sizes, int n_in,
                              void* d_out, int out_size) {
    const float* x   = (const float*)d_in[0];
    const float* sp  = (const float*)d_in[2];
    const float* g1  = (const float*)d_in[3];
    const float* b1  = (const float*)d_in[4];
    const float* g2  = (const float*)d_in[5];
    const float* b2  = (const float*)d_in[6];
    const float* W1  = (const float*)d_in[7];
    const float* bb1 = (const float*)d_in[8];
    const float* W2  = (const float*)d_in[9];
    const float* bb2 = (const float*)d_in[10];
    float* out = (float*)d_out;

    __half *normx, *normxT, *Sh, *h, *t, *W1T, *W2T;
    float *x2;
    cudaGetSymbolAddress((void**)&normx,  g_normx);
    cudaGetSymbolAddress((void**)&normxT, g_normxT);
    cudaGetSymbolAddress((void**)&Sh,     g_Sh);
    cudaGetSymbolAddress((void**)&x2,     g_x2);
    cudaGetSymbolAddress((void**)&h,      g_h);
    cudaGetSymbolAddress((void**)&t,      g_t);
    cudaGetSymbolAddress((void**)&W1T,    g_W1T);
    cudaGetSymbolAddress((void**)&W2T,    g_W2T);

    const int SMEM = 3 * (32768 + 16384);   // 144 KB
    cudaFuncSetAttribute(mma_gemm<0>, cudaFuncAttributeMaxDynamicSharedMemorySize, SMEM);
    cudaFuncSetAttribute(mma_gemm<1>, cudaFuncAttributeMaxDynamicSharedMemorySize, SMEM);
    cudaFuncSetAttribute(mma_gemm<2>, cudaFuncAttributeMaxDynamicSharedMemorySize, SMEM);
    cudaFuncSetAttribute(mma_gemm<3>, cudaFuncAttributeMaxDynamicSharedMemorySize, SMEM);

    const float scale = 0.044194173824159216f;  // 1/sqrt(512)

    // launches 0-4 (keeps the QK^T GEMM at profile index 5)
    layernorm_kernel<<<NROWS / 2, 128>>>(x, g1, b1, normx);                       // 0
    layernorm_kernel<<<NROWS / 2, 128>>>(x + (size_t)(NROWS / 2) * EMB, g1, b1,
                                         normx + (size_t)(NROWS / 2) * EMB);      // 1
    transpose_h2h_kernel<<<dim3(EMB / 32, NROWS / 32), dim3(32, 8)>>>(
        normx, normxT, NROWS, EMB);                                               // 2
    transpose_f2h_kernel<<<dim3(DFF / 32, EMB / 32), dim3(32, 8)>>>(W1, W1T, EMB, DFF);  // 3
    transpose_f2h_kernel<<<dim3(EMB / 32, DFF / 32), dim3(32, 8)>>>(W2, W2T, DFF, EMB);  // 4

    // 5: Sh = half(norm_x @ norm_x^T * scale + SP)    (profiled)
    mma_gemm<0><<<dim3(NROWS / 128, NROWS / 256), 256, SMEM>>>(
        normx, normx, Sh, NROWS, NROWS, EMB, sp, nullptr, scale);

    // 6: attn = softmax(Sh) in place
    softmax_kernel<<<NROWS, 256>>>(Sh);

    // 7: x2 = attn @ norm_x + x    (grid 4 x 32 = 128 CTAs, single wave)
    mma_gemm<1><<<dim3(EMB / 128, NROWS / 256), 256, SMEM>>>(
        Sh, normxT, x2, NROWS, EMB, NROWS, x, nullptr, 1.f);

    // 8: h = LN(x2; g2, b2) -> half
    layernorm_kernel<<<NROWS, 128>>>(x2, g2, b2, h);

    // 9: t = relu(h @ W1 + bb1) -> half
    mma_gemm<2><<<dim3(DFF / 128, NROWS / 256), 256, SMEM>>>(
        h, W1T, t, NROWS, DFF, EMB, nullptr, bb1, 1.f);

    // 10: out = t @ W2 + bb2 + x2    (128 CTAs, single wave)
    mma_gemm<3><<<dim3(EMB / 128, NROWS / 256), 256, SMEM>>>(
        t, W2T, out, NROWS, EMB, DFF, x2, bb2, 1.f);
}

// round 11
// speedup vs baseline: 1.0867x; 1.0867x over previous
#include <cuda_runtime.h>
#include <cuda_fp16.h>
#include <math.h>
#include <stdint.h>

#define NROWS 8192
#define EMB   512
#define DFF   2048

// ---------------- scratch (static device globals; no allocs) ----------------
static __device__ __half g_normx[NROWS * EMB];                 // 8 MB
static __device__ __half g_normxT[EMB * NROWS];                // 8 MB
static __device__ __half g_Sh[(size_t)NROWS * NROWS];          // 128 MB (exp scores, half)
static __device__ float  g_partial[(size_t)NROWS * 256];       // 8 MB  (per-32col partial sums)
static __device__ float  g_rowsum[NROWS];                      // 32 KB
static __device__ float  g_x2[NROWS * EMB];                    // 16 MB
static __device__ __half g_h[NROWS * EMB];                     // 8 MB
static __device__ __half g_t[NROWS * DFF];                     // 32 MB
static __device__ __half g_W1T[(size_t)DFF * EMB];             // 2 MB
static __device__ __half g_W2T[(size_t)EMB * DFF];             // 2 MB

#define EXP_SHIFT 24.0f

// ---------------- helpers ----------------
__device__ __forceinline__ uint32_t smem_u32(const void* p) {
    uint32_t a;
    asm("{ .reg .u64 t; cvta.to.shared.u64 t, %1; cvt.u32.u64 %0, t; }" : "=r"(a) : "l"(p));
    return a;
}
__device__ __forceinline__ void cp16(uint32_t dst, const void* src) {
    asm volatile("cp.async.cg.shared.global [%0], [%1], 16;" :: "r"(dst), "l"(src));
}
__device__ __forceinline__ void ldsm_x4(uint32_t a[4], uint32_t addr) {
    asm volatile("ldmatrix.sync.aligned.m8n8.x4.shared.b16 {%0,%1,%2,%3}, [%4];"
                 : "=r"(a[0]), "=r"(a[1]), "=r"(a[2]), "=r"(a[3]) : "r"(addr));
}
__device__ __forceinline__ void mma_f16(float c[4], const uint32_t a[4], uint32_t b0, uint32_t b1) {
    asm volatile(
        "mma.sync.aligned.m16n8k16.row.col.f32.f16.f16.f32 "
        "{%0,%1,%2,%3}, {%4,%5,%6,%7}, {%8,%9}, {%0,%1,%2,%3};"
        : "+f"(c[0]), "+f"(c[1]), "+f"(c[2]), "+f"(c[3])
        : "r"(a[0]), "r"(a[1]), "r"(a[2]), "r"(a[3]), "r"(b0), "r"(b1));
}

// ---------------------------------------------------------------------------
// LayerNorm: one block per row, 128 threads. fp32 in, half out.
// ---------------------------------------------------------------------------
__global__ void layernorm_kernel(const float* __restrict__ x,
                                 const float* __restrict__ g,
                                 const float* __restrict__ b,
                                 __half* __restrict__ out) {
    const int row = blockIdx.x;
    const int t = threadIdx.x;
    float4 v = reinterpret_cast<const float4*>(x + (size_t)row * EMB)[t];

    float s  = v.x + v.y + v.z + v.w;
    float ss = v.x * v.x + v.y * v.y + v.z * v.z + v.w * v.w;

    __shared__ float red_s[4], red_ss[4];
    #pragma unroll
    for (int o = 16; o; o >>= 1) {
        s  += __shfl_xor_sync(0xffffffffu, s,  o);
        ss += __shfl_xor_sync(0xffffffffu, ss, o);
    }
    if ((t & 31) == 0) { red_s[t >> 5] = s; red_ss[t >> 5] = ss; }
    __syncthreads();
    s  = red_s[0]  + red_s[1]  + red_s[2]  + red_s[3];
    ss = red_ss[0] + red_ss[1] + red_ss[2] + red_ss[3];

    const float mu  = s * (1.0f / EMB);
    const float var = ss * (1.0f / EMB) - mu * mu;
    const float r   = rsqrtf(var + 1e-5f);

    float4 gv = reinterpret_cast<const float4*>(g)[t];
    float4 bv = reinterpret_cast<const float4*>(b)[t];
    __half2 h0 = __floats2half2_rn((v.x - mu) * r * gv.x + bv.x,
                                   (v.y - mu) * r * gv.y + bv.y);
    __half2 h1 = __floats2half2_rn((v.z - mu) * r * gv.z + bv.z,
                                   (v.w - mu) * r * gv.w + bv.w);
    reinterpret_cast<__half2*>(out + (size_t)row * EMB)[2 * t]     = h0;
    reinterpret_cast<__half2*>(out + (size_t)row * EMB)[2 * t + 1] = h1;
}

// ---------------------------------------------------------------------------
// rowsum reduce: one warp per row, sums 256 partials.
// ---------------------------------------------------------------------------
__global__ void rowsum_kernel(const float* __restrict__ partial, float* __restrict__ rowsum) {
    const int row  = blockIdx.x * 8 + (threadIdx.x >> 5);
    const int lane = threadIdx.x & 31;
    const float* p = partial + (size_t)row * 256;
    float s = 0.f;
    #pragma unroll
    for (int i = 0; i < 8; i++) s += p[lane + i * 32];
    #pragma unroll
    for (int o = 16; o; o >>= 1) s += __shfl_xor_sync(0xffffffffu, s, o);
    if (lane == 0) rowsum[row] = s;
}

// ---------------------------------------------------------------------------
// Transposes: out[Cc][R] = in[R][Cc]
// ---------------------------------------------------------------------------
__global__ void transpose_f2h_kernel(const float* __restrict__ in, __half* __restrict__ out,
                                     int R, int Cc) {
    __shared__ float tile[32][34];
    const int bx = blockIdx.x * 32, by = blockIdx.y * 32;
    int x = bx + threadIdx.x;
    #pragma unroll
    for (int i = 0; i < 32; i += 8)
        tile[threadIdx.y + i][threadIdx.x] = in[(size_t)(by + threadIdx.y + i) * Cc + x];
    __syncthreads();
    x = by + threadIdx.x;
    #pragma unroll
    for (int i = 0; i < 32; i += 8)
        out[(size_t)(bx + threadIdx.y + i) * R + x] = __float2half(tile[threadIdx.x][threadIdx.y + i]);
}
__global__ void transpose_h2h_kernel(const __half* __restrict__ in, __half* __restrict__ out,
                                     int R, int Cc) {
    __shared__ __half tile[32][34];
    const int bx = blockIdx.x * 32, by = blockIdx.y * 32;
    int x = bx + threadIdx.x;
    #pragma unroll
    for (int i = 0; i < 32; i += 8)
        tile[threadIdx.y + i][threadIdx.x] = in[(size_t)(by + threadIdx.y + i) * Cc + x];
    __syncthreads();
    x = by + threadIdx.x;
    #pragma unroll
    for (int i = 0; i < 32; i += 8)
        out[(size_t)(bx + threadIdx.y + i) * R + x] = tile[threadIdx.x][threadIdx.y + i];
}

// ---------------------------------------------------------------------------
// fp16 mma.sync GEMM:  D[M,Nn] = A[M,K] * B[Nn,K]^T  (A, B half, K-major).
// CTA 128x128, 8 warps (warp tile 64x32), K-chunk 64, 3-stage cp.async
// pipeline, XOR-swizzled smem, ldmatrix.x4 for A and B.  (R9 config.)
// MODE 0: Sh = half(exp(acc*scale + aux - 24)); warp partial row-sums -> extra
// MODE 1: C = acc / rowsum[r] + aux (f32)   (extra = rowsum)
// MODE 2: C = half(relu(acc + bias))
// MODE 3: C = acc + bias + aux (f32)
// ---------------------------------------------------------------------------
template <int MODE>
__global__ __launch_bounds__(256, 2)
void mma_gemm(const __half* __restrict__ A, const __half* __restrict__ B,
              void* __restrict__ Cv, int M, int Nn, int K,
              const float* __restrict__ aux, const float* __restrict__ bias,
              float scale, float* __restrict__ extra) {
    extern __shared__ char smem[];
    const uint32_t sA = smem_u32(smem);            // 3 x 16 KB
    const uint32_t sB = sA + 3u * 16384u;          // 3 x 16 KB

    const int tid  = threadIdx.x;
    const int lane = tid & 31, wid = tid >> 5;
    const int wm = wid & 1, wn = wid >> 1;         // 2 x 4 warp grid
    const int bm = blockIdx.y * 128, bn = blockIdx.x * 128;
    const int q  = lane & 3, gr = lane >> 2;

    float acc[4][4][4];
    #pragma unroll
    for (int i = 0; i < 4; i++)
        #pragma unroll
        for (int j = 0; j < 4; j++)
            #pragma unroll
            for (int c = 0; c < 4; c++) acc[i][j][c] = 0.f;

    const int a_row_in = ((lane >> 3) & 1) * 8 + (lane & 7);
    const int a_gsel   = lane >> 4;
    const int b_nt_ofs = (lane >> 4);
    const int b_kh     = (lane >> 3) & 1;
    const int b_row_in = lane & 7;

    auto load_chunk = [&](int k0, int stg) {        // k0 in halfs, chunk = 64
        #pragma unroll
        for (int i = 0; i < 4; i++) {
            int idx = tid + i * 256;
            int r = idx >> 3, cg = idx & 7;
            uint32_t off = (uint32_t)(r * 128 + ((cg ^ (r & 7)) << 4));
            cp16(sA + (uint32_t)stg * 16384u + off,
                 A + (size_t)(bm + r) * K + k0 + cg * 8);
        }
        #pragma unroll
        for (int i = 0; i < 4; i++) {
            int idx = tid + i * 256;
            int r = idx >> 3, cg = idx & 7;
            uint32_t off = (uint32_t)(r * 128 + ((cg ^ (r & 7)) << 4));
            cp16(sB + (uint32_t)stg * 16384u + off,
                 B + (size_t)(bn + r) * K + k0 + cg * 8);
        }
        asm volatile("cp.async.commit_group;");
    };

    const int nk = K / 64;
    load_chunk(0, 0);
    load_chunk(64, 1);

    for (int kc = 0; kc < nk; kc++) {
        if (kc == nk - 1) asm volatile("cp.async.wait_group %0;" :: "n"(0));
        else              asm volatile("cp.async.wait_group %0;" :: "n"(1));
        __syncthreads();

        const int stg = kc % 3;
        const uint32_t aB = sA + (uint32_t)stg * 16384u;
        const uint32_t bB = sB + (uint32_t)stg * 16384u;

        #pragma unroll
        for (int ks = 0; ks < 4; ks++) {
            uint32_t a[4][4];
            #pragma unroll
            for (int mt = 0; mt < 4; mt++) {
                const int row = wm * 64 + mt * 16 + a_row_in;
                const uint32_t g = (uint32_t)((2 * ks + a_gsel) ^ (row & 7));
                ldsm_x4(a[mt], aB + (uint32_t)(row * 128) + (g << 4));
            }
            uint32_t bfr[2][4];
            #pragma unroll
            for (int p = 0; p < 2; p++) {
                const int nt = 2 * p + b_nt_ofs;
                const int n  = wn * 32 + nt * 8 + b_row_in;
                const uint32_t g = (uint32_t)((2 * ks + b_kh) ^ (n & 7));
                ldsm_x4(bfr[p], bB + (uint32_t)(n * 128) + (g << 4));
            }
            #pragma unroll
            for (int mt = 0; mt < 4; mt++) {
                mma_f16(acc[mt][0], a[mt], bfr[0][0], bfr[0][1]);
                mma_f16(acc[mt][1], a[mt], bfr[0][2], bfr[0][3]);
                mma_f16(acc[mt][2], a[mt], bfr[1][0], bfr[1][1]);
                mma_f16(acc[mt][3], a[mt], bfr[1][2], bfr[1][3]);
            }
        }

        if (kc + 2 < nk) load_chunk((kc + 2) * 64, (kc + 2) % 3);
    }

    // ---------------- epilogue ----------------
    #pragma unroll
    for (int mt = 0; mt < 4; mt++) {
        #pragma unroll
        for (int half_ = 0; half_ < 2; half_++) {
            const int r = bm + wm * 64 + mt * 16 + gr + half_ * 8;
            const size_t ro = (size_t)r * Nn;
            float rsum = 0.f;
            float inv  = 0.f;
            if (MODE == 1) inv = 1.0f / extra[r];
            #pragma unroll
            for (int nt = 0; nt < 4; nt++) {
                const int c0 = bn + wn * 32 + nt * 8 + 2 * q;
                float v0 = acc[mt][nt][2 * half_ + 0];
                float v1 = acc[mt][nt][2 * half_ + 1];
                if (MODE == 0) {
                    float2 a2 = *reinterpret_cast<const float2*>(aux + ro + c0);
                    float e0 = __expf(v0 * scale + a2.x - EXP_SHIFT);
                    float e1 = __expf(v1 * scale + a2.y - EXP_SHIFT);
                    *reinterpret_cast<__half2*>((__half*)Cv + ro + c0) =
                        __floats2half2_rn(e0, e1);
                    rsum += e0 + e1;
                } else if (MODE == 1) {
                    float2 a2 = *reinterpret_cast<const float2*>(aux + ro + c0);
                    *reinterpret_cast<float2*>((float*)Cv + ro + c0) =
                        make_float2(v0 * inv + a2.x, v1 * inv + a2.y);
                } else if (MODE == 2) {
                    float2 b2 = *reinterpret_cast<const float2*>(bias + c0);
                    *reinterpret_cast<__half2*>((__half*)Cv + ro + c0) =
                        __floats2half2_rn(fmaxf(v0 + b2.x, 0.f), fmaxf(v1 + b2.y, 0.f));
                } else {
                    float2 a2 = *reinterpret_cast<const float2*>(aux + ro + c0);
                    float2 b2 = *reinterpret_cast<const float2*>(bias + c0);
                    *reinterpret_cast<float2*>((float*)Cv + ro + c0) =
                        make_float2(v0 + b2.x + a2.x, v1 + b2.y + a2.y);
                }
            }
            if (MODE == 0) {
                // reduce 8-col partial across q lanes -> 32-col sum for this row
                rsum += __shfl_xor_sync(0xffffffffu, rsum, 1);
                rsum += __shfl_xor_sync(0xffffffffu, rsum, 2);
                if (q == 0)
                    extra[(size_t)r * 256 + (size_t)(blockIdx.x * 4 + wn)] = rsum;
            }
        }
    }
}

// ---------------------------------------------------------------------------
extern "C" void kernel_launch(void* const* d_in, const int* in_sizes, int n_in,
                              void* d_out, int out_size) {
    const float* x   = (const float*)d_in[0];
    const float* sp  = (const float*)d_in[2];
    const float* g1  = (const float*)d_in[3];
    const float* b1  = (const float*)d_in[4];
    const float* g2  = (const float*)d_in[5];
    const float* b2  = (const float*)d_in[6];
    const float* W1  = (const float*)d_in[7];
    const float* bb1 = (const float*)d_in[8];
    const float* W2  = (const float*)d_in[9];
    const float* bb2 = (const float*)d_in[10];
    float* out = (float*)d_out;

    __half *normx, *normxT, *Sh, *h, *t, *W1T, *W2T;
    float *x2, *partial, *rowsum;
    cudaGetSymbolAddress((void**)&normx,   g_normx);
    cudaGetSymbolAddress((void**)&normxT,  g_normxT);
    cudaGetSymbolAddress((void**)&Sh,      g_Sh);
    cudaGetSymbolAddress((void**)&partial, g_partial);
    cudaGetSymbolAddress((void**)&rowsum,  g_rowsum);
    cudaGetSymbolAddress((void**)&x2,      g_x2);
    cudaGetSymbolAddress((void**)&h,       g_h);
    cudaGetSymbolAddress((void**)&t,       g_t);
    cudaGetSymbolAddress((void**)&W1T,     g_W1T);
    cudaGetSymbolAddress((void**)&W2T,     g_W2T);

    const int SMEM = 96 * 1024;   // 3-stage x (16 KB A + 16 KB B)
    cudaFuncSetAttribute(mma_gemm<0>, cudaFuncAttributeMaxDynamicSharedMemorySize, SMEM);
    cudaFuncSetAttribute(mma_gemm<1>, cudaFuncAttributeMaxDynamicSharedMemorySize, SMEM);
    cudaFuncSetAttribute(mma_gemm<2>, cudaFuncAttributeMaxDynamicSharedMemorySize, SMEM);
    cudaFuncSetAttribute(mma_gemm<3>, cudaFuncAttributeMaxDynamicSharedMemorySize, SMEM);

    const float scale = 0.044194173824159216f;  // 1/sqrt(512)

    // launches 0-4 (keeps the QK^T GEMM at profile index 5)
    layernorm_kernel<<<NROWS / 2, 128>>>(x, g1, b1, normx);                       // 0
    layernorm_kernel<<<NROWS / 2, 128>>>(x + (size_t)(NROWS / 2) * EMB, g1, b1,
                                         normx + (size_t)(NROWS / 2) * EMB);      // 1
    transpose_h2h_kernel<<<dim3(EMB / 32, NROWS / 32), dim3(32, 8)>>>(
        normx, normxT, NROWS, EMB);                                               // 2
    transpose_f2h_kernel<<<dim3(DFF / 32, EMB / 32), dim3(32, 8)>>>(W1, W1T, EMB, DFF);  // 3
    transpose_f2h_kernel<<<dim3(EMB / 32, DFF / 32), dim3(32, 8)>>>(W2, W2T, DFF, EMB);  // 4

    // 5: Sh = half(exp(norm_x @ norm_x^T * scale + SP - 24)), partial row sums
    mma_gemm<0><<<dim3(NROWS / 128, NROWS / 128), 256, SMEM>>>(
        normx, normx, Sh, NROWS, NROWS, EMB, sp, nullptr, scale, partial);

    // 6: rowsum = sum of partials
    rowsum_kernel<<<NROWS / 8, 256>>>(partial, rowsum);

    // 7: x2 = (expS @ norm_x) / rowsum + x
    mma_gemm<1><<<dim3(EMB / 128, NROWS / 128), 256, SMEM>>>(
        Sh, normxT, x2, NROWS, EMB, NROWS, x, nullptr, 1.f, rowsum);

    // 8: h = LN(x2; g2, b2) -> half
    layernorm_kernel<<<NROWS, 128>>>(x2, g2, b2, h);

    // 9: t = relu(h @ W1 + bb1) -> half
    mma_gemm<2><<<dim3(DFF / 128, NROWS / 128), 256, SMEM>>>(
        h, W1T, t, NROWS, DFF, EMB, nullptr, bb1, 1.f, nullptr);

    // 10: out = t @ W2 + bb2 + x2
    mma_gemm<3><<<dim3(EMB / 128, NROWS / 128), 256, SMEM>>>(
        t, W2T, out, NROWS, EMB, DFF, x2, bb2, 1.f, nullptr);
}

// round 12
// speedup vs baseline: 1.1611x; 1.0684x over previous
#include <cuda_runtime.h>
#include <cuda_fp16.h>
#include <math.h>
#include <stdint.h>

#define NROWS 8192
#define EMB   512
#define DFF   2048

// ---------------- scratch (static device globals; no allocs) ----------------
static __device__ __half g_normx[NROWS * EMB];                 // 8 MB
static __device__ __half g_normxT[EMB * NROWS];                // 8 MB
static __device__ __half g_Sh[(size_t)NROWS * NROWS];          // 128 MB (exp scores, half)
static __device__ float  g_partial[(size_t)NROWS * 256];       // 8 MB
static __device__ float  g_rowsum[NROWS];                      // 32 KB
static __device__ float  g_x2[NROWS * EMB];                    // 16 MB
static __device__ __half g_h[NROWS * EMB];                     // 8 MB
static __device__ __half g_t[NROWS * DFF];                     // 32 MB
static __device__ __half g_W1T[(size_t)DFF * EMB];             // 2 MB
static __device__ __half g_W2T[(size_t)EMB * DFF];             // 2 MB

#define EXP_SHIFT 24.0f

// ---------------- helpers ----------------
__device__ __forceinline__ uint32_t smem_u32(const void* p) {
    uint32_t a;
    asm("{ .reg .u64 t; cvta.to.shared.u64 t, %1; cvt.u32.u64 %0, t; }" : "=r"(a) : "l"(p));
    return a;
}
__device__ __forceinline__ void cp16(uint32_t dst, const void* src) {
    asm volatile("cp.async.cg.shared.global [%0], [%1], 16;" :: "r"(dst), "l"(src));
}
__device__ __forceinline__ void ldsm_x4(uint32_t a[4], uint32_t addr) {
    asm volatile("ldmatrix.sync.aligned.m8n8.x4.shared.b16 {%0,%1,%2,%3}, [%4];"
                 : "=r"(a[0]), "=r"(a[1]), "=r"(a[2]), "=r"(a[3]) : "r"(addr));
}
__device__ __forceinline__ void mma_f16(float c[4], const uint32_t a[4], uint32_t b0, uint32_t b1) {
    asm volatile(
        "mma.sync.aligned.m16n8k16.row.col.f32.f16.f16.f32 "
        "{%0,%1,%2,%3}, {%4,%5,%6,%7}, {%8,%9}, {%0,%1,%2,%3};"
        : "+f"(c[0]), "+f"(c[1]), "+f"(c[2]), "+f"(c[3])
        : "r"(a[0]), "r"(a[1]), "r"(a[2]), "r"(a[3]), "r"(b0), "r"(b1));
}

// ---------------------------------------------------------------------------
// LayerNorm: one block per row, 128 threads. fp32 in, half out.
// ---------------------------------------------------------------------------
__global__ void layernorm_kernel(const float* __restrict__ x,
                                 const float* __restrict__ g,
                                 const float* __restrict__ b,
                                 __half* __restrict__ out) {
    const int row = blockIdx.x;
    const int t = threadIdx.x;
    float4 v = reinterpret_cast<const float4*>(x + (size_t)row * EMB)[t];

    float s  = v.x + v.y + v.z + v.w;
    float ss = v.x * v.x + v.y * v.y + v.z * v.z + v.w * v.w;

    __shared__ float red_s[4], red_ss[4];
    #pragma unroll
    for (int o = 16; o; o >>= 1) {
        s  += __shfl_xor_sync(0xffffffffu, s,  o);
        ss += __shfl_xor_sync(0xffffffffu, ss, o);
    }
    if ((t & 31) == 0) { red_s[t >> 5] = s; red_ss[t >> 5] = ss; }
    __syncthreads();
    s  = red_s[0]  + red_s[1]  + red_s[2]  + red_s[3];
    ss = red_ss[0] + red_ss[1] + red_ss[2] + red_ss[3];

    const float mu  = s * (1.0f / EMB);
    const float var = ss * (1.0f / EMB) - mu * mu;
    const float r   = rsqrtf(var + 1e-5f);

    float4 gv = reinterpret_cast<const float4*>(g)[t];
    float4 bv = reinterpret_cast<const float4*>(b)[t];
    __half2 h0 = __floats2half2_rn((v.x - mu) * r * gv.x + bv.x,
                                   (v.y - mu) * r * gv.y + bv.y);
    __half2 h1 = __floats2half2_rn((v.z - mu) * r * gv.z + bv.z,
                                   (v.w - mu) * r * gv.w + bv.w);
    reinterpret_cast<__half2*>(out + (size_t)row * EMB)[2 * t]     = h0;
    reinterpret_cast<__half2*>(out + (size_t)row * EMB)[2 * t + 1] = h1;
}

// ---------------------------------------------------------------------------
// rowsum reduce: one warp per row, sums 256 partials.
// ---------------------------------------------------------------------------
__global__ void rowsum_kernel(const float* __restrict__ partial, float* __restrict__ rowsum) {
    const int row  = blockIdx.x * 8 + (threadIdx.x >> 5);
    const int lane = threadIdx.x & 31;
    const float* p = partial + (size_t)row * 256;
    float s = 0.f;
    #pragma unroll
    for (int i = 0; i < 8; i++) s += p[lane + i * 32];
    #pragma unroll
    for (int o = 16; o; o >>= 1) s += __shfl_xor_sync(0xffffffffu, s, o);
    if (lane == 0) rowsum[row] = s;
}

// ---------------------------------------------------------------------------
// Transposes: out[Cc][R] = in[R][Cc]
// ---------------------------------------------------------------------------
__global__ void transpose_f2h_kernel(const float* __restrict__ in, __half* __restrict__ out,
                                     int R, int Cc) {
    __shared__ float tile[32][34];
    const int bx = blockIdx.x * 32, by = blockIdx.y * 32;
    int x = bx + threadIdx.x;
    #pragma unroll
    for (int i = 0; i < 32; i += 8)
        tile[threadIdx.y + i][threadIdx.x] = in[(size_t)(by + threadIdx.y + i) * Cc + x];
    __syncthreads();
    x = by + threadIdx.x;
    #pragma unroll
    for (int i = 0; i < 32; i += 8)
        out[(size_t)(bx + threadIdx.y + i) * R + x] = __float2half(tile[threadIdx.x][threadIdx.y + i]);
}
__global__ void transpose_h2h_kernel(const __half* __restrict__ in, __half* __restrict__ out,
                                     int R, int Cc) {
    __shared__ __half tile[32][34];
    const int bx = blockIdx.x * 32, by = blockIdx.y * 32;
    int x = bx + threadIdx.x;
    #pragma unroll
    for (int i = 0; i < 32; i += 8)
        tile[threadIdx.y + i][threadIdx.x] = in[(size_t)(by + threadIdx.y + i) * Cc + x];
    __syncthreads();
    x = by + threadIdx.x;
    #pragma unroll
    for (int i = 0; i < 32; i += 8)
        out[(size_t)(bx + threadIdx.y + i) * R + x] = tile[threadIdx.x][threadIdx.y + i];
}

// ===========================================================================
// Shared GEMM mainloop config: CTA 128x128, 8 warps (warp tile 64x32),
// K-chunk 64, 3-stage cp.async, XOR-swizzled smem, ldmatrix.x4 A + B.
// ===========================================================================
#define GEMM_MAINLOOP(A_, B_, K_, bm_, bn_)                                          \
    const uint32_t sA = smem_u32(smem);                                              \
    const uint32_t sB = sA + 3u * 16384u;                                            \
    const int tid  = threadIdx.x;                                                    \
    const int lane = tid & 31, wid = tid >> 5;                                       \
    const int wm = wid & 1, wn = wid >> 1;                                           \
    const int q  = lane & 3, gr = lane >> 2;                                         \
    float acc[4][4][4];                                                              \
    _Pragma("unroll") for (int i = 0; i < 4; i++)                                    \
        _Pragma("unroll") for (int j = 0; j < 4; j++)                                \
            _Pragma("unroll") for (int c = 0; c < 4; c++) acc[i][j][c] = 0.f;        \
    const int a_row_in = ((lane >> 3) & 1) * 8 + (lane & 7);                         \
    const int a_gsel   = lane >> 4;                                                  \
    const int b_nt_ofs = (lane >> 4);                                                \
    const int b_kh     = (lane >> 3) & 1;                                            \
    const int b_row_in = lane & 7;                                                   \
    auto load_chunk = [&](int k0, int stg) {                                         \
        _Pragma("unroll") for (int i = 0; i < 4; i++) {                              \
            int idx = tid + i * 256;                                                 \
            int r = idx >> 3, cg = idx & 7;                                          \
            uint32_t off = (uint32_t)(r * 128 + ((cg ^ (r & 7)) << 4));              \
            cp16(sA + (uint32_t)stg * 16384u + off,                                  \
                 (A_) + (size_t)((bm_) + r) * (K_) + k0 + cg * 8);                   \
        }                                                                            \
        _Pragma("unroll") for (int i = 0; i < 4; i++) {                              \
            int idx = tid + i * 256;                                                 \
            int r = idx >> 3, cg = idx & 7;                                          \
            uint32_t off = (uint32_t)(r * 128 + ((cg ^ (r & 7)) << 4));              \
            cp16(sB + (uint32_t)stg * 16384u + off,                                  \
                 (B_) + (size_t)((bn_) + r) * (K_) + k0 + cg * 8);                   \
        }                                                                            \
        asm volatile("cp.async.commit_group;");                                      \
    };                                                                               \
    const int nk = (K_) / 64;                                                        \
    load_chunk(0, 0);                                                                \
    load_chunk(64, 1);                                                               \
    for (int kc = 0; kc < nk; kc++) {                                                \
        if (kc == nk - 1) asm volatile("cp.async.wait_group %0;" :: "n"(0));         \
        else              asm volatile("cp.async.wait_group %0;" :: "n"(1));         \
        __syncthreads();                                                             \
        const int stg = kc % 3;                                                      \
        const uint32_t aB = sA + (uint32_t)stg * 16384u;                             \
        const uint32_t bB = sB + (uint32_t)stg * 16384u;                             \
        _Pragma("unroll") for (int ks = 0; ks < 4; ks++) {                           \
            uint32_t a[4][4];                                                        \
            _Pragma("unroll") for (int mt = 0; mt < 4; mt++) {                       \
                const int row = wm * 64 + mt * 16 + a_row_in;                        \
                const uint32_t g = (uint32_t)((2 * ks + a_gsel) ^ (row & 7));        \
                ldsm_x4(a[mt], aB + (uint32_t)(row * 128) + (g << 4));               \
            }                                                                        \
            uint32_t bfr[2][4];                                                      \
            _Pragma("unroll") for (int p = 0; p < 2; p++) {                          \
                const int nt = 2 * p + b_nt_ofs;                                     \
                const int n  = wn * 32 + nt * 8 + b_row_in;                          \
                const uint32_t g = (uint32_t)((2 * ks + b_kh) ^ (n & 7));            \
                ldsm_x4(bfr[p], bB + (uint32_t)(n * 128) + (g << 4));                \
            }                                                                        \
            _Pragma("unroll") for (int mt = 0; mt < 4; mt++) {                       \
                mma_f16(acc[mt][0], a[mt], bfr[0][0], bfr[0][1]);                    \
                mma_f16(acc[mt][1], a[mt], bfr[0][2], bfr[0][3]);                    \
                mma_f16(acc[mt][2], a[mt], bfr[1][0], bfr[1][1]);                    \
                mma_f16(acc[mt][3], a[mt], bfr[1][2], bfr[1][3]);                    \
            }                                                                        \
        }                                                                            \
        if (kc + 2 < nk) load_chunk((kc + 2) * 64, (kc + 2) % 3);                    \
    }

// ---------------------------------------------------------------------------
// Symmetric QK kernel: computes only tiles with bj >= bi.
// Normal epilogue writes exp tile + warp partials; for bj > bi the fp32 acc
// is staged (transposed) in smem and a mirror pass writes the (bj,bi) tile
// with its own sp entries + per-thread mirror partials.
// ---------------------------------------------------------------------------
__global__ __launch_bounds__(256, 2)
void qk_gemm(const __half* __restrict__ A,
             __half* __restrict__ Sh, const float* __restrict__ sp,
             float* __restrict__ partial, float scale) {
    const int bi = blockIdx.y, bj = blockIdx.x;
    if (bj < bi) return;
    const int bm = bi * 128, bn = bj * 128;
    extern __shared__ char smem[];

    GEMM_MAINLOOP(A, A, EMB, bm, bn)

    // ---- normal epilogue (upper tile) ----
    #pragma unroll
    for (int mt = 0; mt < 4; mt++) {
        #pragma unroll
        for (int half_ = 0; half_ < 2; half_++) {
            const int r = bm + wm * 64 + mt * 16 + gr + half_ * 8;
            const size_t ro = (size_t)r * NROWS;
            float rsum = 0.f;
            #pragma unroll
            for (int nt = 0; nt < 4; nt++) {
                const int c0 = bn + wn * 32 + nt * 8 + 2 * q;
                float v0 = acc[mt][nt][2 * half_ + 0];
                float v1 = acc[mt][nt][2 * half_ + 1];
                float2 a2 = *reinterpret_cast<const float2*>(sp + ro + c0);
                float e0 = __expf(v0 * scale + a2.x - EXP_SHIFT);
                float e1 = __expf(v1 * scale + a2.y - EXP_SHIFT);
                *reinterpret_cast<__half2*>(Sh + ro + c0) = __floats2half2_rn(e0, e1);
                rsum += e0 + e1;
            }
            rsum += __shfl_xor_sync(0xffffffffu, rsum, 1);
            rsum += __shfl_xor_sync(0xffffffffu, rsum, 2);
            if (q == 0)
                partial[(size_t)r * 256 + (size_t)(bj * 4 + wn)] = rsum;
        }
    }

    // ---- mirror epilogue (lower tile), bj > bi only ----
    if (bj > bi) {
        float* smT = reinterpret_cast<float*>(smem);   // 128 cols x stride 132 fp32
        __syncthreads();   // mainloop smem no longer needed
        #pragma unroll
        for (int mt = 0; mt < 4; mt++) {
            #pragma unroll
            for (int half_ = 0; half_ < 2; half_++) {
                const int r = wm * 64 + mt * 16 + gr + half_ * 8;   // local row
                #pragma unroll
                for (int nt = 0; nt < 4; nt++) {
                    const int c = wn * 32 + nt * 8 + 2 * q;          // local col
                    smT[(size_t)c * 132 + r]       = acc[mt][nt][2 * half_ + 0];
                    smT[(size_t)(c + 1) * 132 + r] = acc[mt][nt][2 * half_ + 1];
                }
            }
        }
        __syncthreads();

        const int c  = tid >> 1;          // local transposed row (orig col) 0..127
        const int hf = tid & 1;           // which 64-col half
        const int cb = hf * 64;
        const size_t orow = (size_t)(bn + c) * NROWS + bm + cb;
        const float* srow = smT + (size_t)c * 132 + cb;
        const float* sprow = sp + orow;
        float s0 = 0.f, s1 = 0.f;
        #pragma unroll
        for (int i = 0; i < 64; i += 8) {
            float4 f0 = *reinterpret_cast<const float4*>(srow + i);
            float4 f1 = *reinterpret_cast<const float4*>(srow + i + 4);
            float4 p0 = *reinterpret_cast<const float4*>(sprow + i);
            float4 p1 = *reinterpret_cast<const float4*>(sprow + i + 4);
            float e0 = __expf(f0.x * scale + p0.x - EXP_SHIFT);
            float e1 = __expf(f0.y * scale + p0.y - EXP_SHIFT);
            float e2 = __expf(f0.z * scale + p0.z - EXP_SHIFT);
            float e3 = __expf(f0.w * scale + p0.w - EXP_SHIFT);
            float e4 = __expf(f1.x * scale + p1.x - EXP_SHIFT);
            float e5 = __expf(f1.y * scale + p1.y - EXP_SHIFT);
            float e6 = __expf(f1.z * scale + p1.z - EXP_SHIFT);
            float e7 = __expf(f1.w * scale + p1.w - EXP_SHIFT);
            float sum8 = ((e0 + e1) + (e2 + e3)) + ((e4 + e5) + (e6 + e7));
            if (i < 32) s0 += sum8; else s1 += sum8;
            __half2 o[4];
            o[0] = __floats2half2_rn(e0, e1); o[1] = __floats2half2_rn(e2, e3);
            o[2] = __floats2half2_rn(e4, e5); o[3] = __floats2half2_rn(e6, e7);
            *reinterpret_cast<uint4*>(Sh + orow + i) = *reinterpret_cast<uint4*>(o);
        }
        partial[(size_t)(bn + c) * 256 + (size_t)((bm >> 5) + hf * 2 + 0)] = s0;
        partial[(size_t)(bn + c) * 256 + (size_t)((bm >> 5) + hf * 2 + 1)] = s1;
    }
}

// ---------------------------------------------------------------------------
// Generic GEMM (modes 1-3), R9/R11 config.
// MODE 1: C = acc / rowsum[r] + aux (f32)
// MODE 2: C = half(relu(acc + bias))
// MODE 3: C = acc + bias + aux (f32)
// ---------------------------------------------------------------------------
template <int MODE>
__global__ __launch_bounds__(256, 2)
void mma_gemm(const __half* __restrict__ A, const __half* __restrict__ B,
              void* __restrict__ Cv, int M, int Nn, int K,
              const float* __restrict__ aux, const float* __restrict__ bias,
              const float* __restrict__ extra) {
    const int bm = blockIdx.y * 128, bn = blockIdx.x * 128;
    extern __shared__ char smem[];

    GEMM_MAINLOOP(A, B, K, bm, bn)

    #pragma unroll
    for (int mt = 0; mt < 4; mt++) {
        #pragma unroll
        for (int half_ = 0; half_ < 2; half_++) {
            const int r = bm + wm * 64 + mt * 16 + gr + half_ * 8;
            const size_t ro = (size_t)r * Nn;
            float inv = 0.f;
            if (MODE == 1) inv = 1.0f / extra[r];
            #pragma unroll
            for (int nt = 0; nt < 4; nt++) {
                const int c0 = bn + wn * 32 + nt * 8 + 2 * q;
                float v0 = acc[mt][nt][2 * half_ + 0];
                float v1 = acc[mt][nt][2 * half_ + 1];
                if (MODE == 1) {
                    float2 a2 = *reinterpret_cast<const float2*>(aux + ro + c0);
                    *reinterpret_cast<float2*>((float*)Cv + ro + c0) =
                        make_float2(v0 * inv + a2.x, v1 * inv + a2.y);
                } else if (MODE == 2) {
                    float2 b2 = *reinterpret_cast<const float2*>(bias + c0);
                    *reinterpret_cast<__half2*>((__half*)Cv + ro + c0) =
                        __floats2half2_rn(fmaxf(v0 + b2.x, 0.f), fmaxf(v1 + b2.y, 0.f));
                } else {
                    float2 a2 = *reinterpret_cast<const float2*>(aux + ro + c0);
                    float2 b2 = *reinterpret_cast<const float2*>(bias + c0);
                    *reinterpret_cast<float2*>((float*)Cv + ro + c0) =
                        make_float2(v0 + b2.x + a2.x, v1 + b2.y + a2.y);
                }
            }
        }
    }
}

// ---------------------------------------------------------------------------
extern "C" void kernel_launch(void* const* d_in, const int* in_sizes, int n_in,
                              void* d_out, int out_size) {
    const float* x   = (const float*)d_in[0];
    const float* sp  = (const float*)d_in[2];
    const float* g1  = (const float*)d_in[3];
    const float* b1  = (const float*)d_in[4];
    const float* g2  = (const float*)d_in[5];
    const float* b2  = (const float*)d_in[6];
    const float* W1  = (const float*)d_in[7];
    const float* bb1 = (const float*)d_in[8];
    const float* W2  = (const float*)d_in[9];
    const float* bb2 = (const float*)d_in[10];
    float* out = (float*)d_out;

    __half *normx, *normxT, *Sh, *h, *t, *W1T, *W2T;
    float *x2, *partial, *rowsum;
    cudaGetSymbolAddress((void**)&normx,   g_normx);
    cudaGetSymbolAddress((void**)&normxT,  g_normxT);
    cudaGetSymbolAddress((void**)&Sh,      g_Sh);
    cudaGetSymbolAddress((void**)&partial, g_partial);
    cudaGetSymbolAddress((void**)&rowsum,  g_rowsum);
    cudaGetSymbolAddress((void**)&x2,      g_x2);
    cudaGetSymbolAddress((void**)&h,       g_h);
    cudaGetSymbolAddress((void**)&t,       g_t);
    cudaGetSymbolAddress((void**)&W1T,     g_W1T);
    cudaGetSymbolAddress((void**)&W2T,     g_W2T);

    const int SMEM = 96 * 1024;   // 3-stage x 32 KB; also covers 128x132 fp32 stage
    cudaFuncSetAttribute(qk_gemm,     cudaFuncAttributeMaxDynamicSharedMemorySize, SMEM);
    cudaFuncSetAttribute(mma_gemm<1>, cudaFuncAttributeMaxDynamicSharedMemorySize, SMEM);
    cudaFuncSetAttribute(mma_gemm<2>, cudaFuncAttributeMaxDynamicSharedMemorySize, SMEM);
    cudaFuncSetAttribute(mma_gemm<3>, cudaFuncAttributeMaxDynamicSharedMemorySize, SMEM);

    const float scale = 0.044194173824159216f;  // 1/sqrt(512)

    // launches 0-4 (keeps the QK^T GEMM at profile index 5)
    layernorm_kernel<<<NROWS / 2, 128>>>(x, g1, b1, normx);                       // 0
    layernorm_kernel<<<NROWS / 2, 128>>>(x + (size_t)(NROWS / 2) * EMB, g1, b1,
                                         normx + (size_t)(NROWS / 2) * EMB);      // 1
    transpose_h2h_kernel<<<dim3(EMB / 32, NROWS / 32), dim3(32, 8)>>>(
        normx, normxT, NROWS, EMB);                                               // 2
    transpose_f2h_kernel<<<dim3(DFF / 32, EMB / 32), dim3(32, 8)>>>(W1, W1T, EMB, DFF);  // 3
    transpose_f2h_kernel<<<dim3(EMB / 32, DFF / 32), dim3(32, 8)>>>(W2, W2T, DFF, EMB);  // 4

    // 5: symmetric QK: Sh = half(exp(S*scale + SP - 24)) + partial row sums
    qk_gemm<<<dim3(NROWS / 128, NROWS / 128), 256, SMEM>>>(
        normx, Sh, sp, partial, scale);

    // 6: rowsum = sum of partials
    rowsum_kernel<<<NROWS / 8, 256>>>(partial, rowsum);

    // 7: x2 = (expS @ norm_x) / rowsum + x
    mma_gemm<1><<<dim3(EMB / 128, NROWS / 128), 256, SMEM>>>(
        Sh, normxT, x2, NROWS, EMB, NROWS, x, nullptr, rowsum);

    // 8: h = LN(x2; g2, b2) -> half
    layernorm_kernel<<<NROWS, 128>>>(x2, g2, b2, h);

    // 9: t = relu(h @ W1 + bb1) -> half
    mma_gemm<2><<<dim3(DFF / 128, NROWS / 128), 256, SMEM>>>(
        h, W1T, t, NROWS, DFF, EMB, nullptr, bb1, nullptr);

    // 10: out = t @ W2 + bb2 + x2
    mma_gemm<3><<<dim3(EMB / 128, NROWS / 128), 256, SMEM>>>(
        t, W2T, out, NROWS, EMB, DFF, x2, bb2, nullptr);
}

// round 13
// speedup vs baseline: 1.7475x; 1.5051x over previous
#include <cuda_runtime.h>
#include <cuda_fp16.h>
#include <math.h>
#include <stdint.h>

#define NROWS 8192
#define EMB   512
#define DFF   2048
#define NT64  (NROWS / 128)   // 64 row/col tiles

// ---------------- scratch (static device globals; no allocs) ----------------
static __device__ __half g_normx[NROWS * EMB];                 // 8 MB
static __device__ __half g_normxT[EMB * NROWS];                // 8 MB
static __device__ __half g_Sh[(size_t)NROWS * NROWS];          // 128 MB (exp scores, half)
static __device__ float  g_partial[(size_t)NROWS * 256];       // 8 MB
static __device__ float  g_rowsum[NROWS];                      // 32 KB
static __device__ int    g_flag[NT64 * NT64];                  // nonzero-tile flags
static __device__ int    g_list[NT64 * NT64];                  // compacted col-tile lists
static __device__ int    g_cnt[NT64];                          // list lengths
static __device__ float  g_x2[NROWS * EMB];                    // 16 MB
static __device__ __half g_h[NROWS * EMB];                     // 8 MB
static __device__ __half g_t[NROWS * DFF];                     // 32 MB
static __device__ __half g_W1T[(size_t)DFF * EMB];             // 2 MB
static __device__ __half g_W2T[(size_t)EMB * DFF];             // 2 MB

#define EXP_SHIFT 24.0f

// ---------------- helpers ----------------
__device__ __forceinline__ uint32_t smem_u32(const void* p) {
    uint32_t a;
    asm("{ .reg .u64 t; cvta.to.shared.u64 t, %1; cvt.u32.u64 %0, t; }" : "=r"(a) : "l"(p));
    return a;
}
__device__ __forceinline__ void cp16(uint32_t dst, const void* src) {
    asm volatile("cp.async.cg.shared.global [%0], [%1], 16;" :: "r"(dst), "l"(src));
}
__device__ __forceinline__ void ldsm_x4(uint32_t a[4], uint32_t addr) {
    asm volatile("ldmatrix.sync.aligned.m8n8.x4.shared.b16 {%0,%1,%2,%3}, [%4];"
                 : "=r"(a[0]), "=r"(a[1]), "=r"(a[2]), "=r"(a[3]) : "r"(addr));
}
__device__ __forceinline__ void mma_f16(float c[4], const uint32_t a[4], uint32_t b0, uint32_t b1) {
    asm volatile(
        "mma.sync.aligned.m16n8k16.row.col.f32.f16.f16.f32 "
        "{%0,%1,%2,%3}, {%4,%5,%6,%7}, {%8,%9}, {%0,%1,%2,%3};"
        : "+f"(c[0]), "+f"(c[1]), "+f"(c[2]), "+f"(c[3])
        : "r"(a[0]), "r"(a[1]), "r"(a[2]), "r"(a[3]), "r"(b0), "r"(b1));
}

// ---------------------------------------------------------------------------
// LayerNorm: one block per row, 128 threads. fp32 in, half out.
// ---------------------------------------------------------------------------
__global__ void layernorm_kernel(const float* __restrict__ x,
                                 const float* __restrict__ g,
                                 const float* __restrict__ b,
                                 __half* __restrict__ out) {
    const int row = blockIdx.x;
    const int t = threadIdx.x;
    float4 v = reinterpret_cast<const float4*>(x + (size_t)row * EMB)[t];

    float s  = v.x + v.y + v.z + v.w;
    float ss = v.x * v.x + v.y * v.y + v.z * v.z + v.w * v.w;

    __shared__ float red_s[4], red_ss[4];
    #pragma unroll
    for (int o = 16; o; o >>= 1) {
        s  += __shfl_xor_sync(0xffffffffu, s,  o);
        ss += __shfl_xor_sync(0xffffffffu, ss, o);
    }
    if ((t & 31) == 0) { red_s[t >> 5] = s; red_ss[t >> 5] = ss; }
    __syncthreads();
    s  = red_s[0]  + red_s[1]  + red_s[2]  + red_s[3];
    ss = red_ss[0] + red_ss[1] + red_ss[2] + red_ss[3];

    const float mu  = s * (1.0f / EMB);
    const float var = ss * (1.0f / EMB) - mu * mu;
    const float r   = rsqrtf(var + 1e-5f);

    float4 gv = reinterpret_cast<const float4*>(g)[t];
    float4 bv = reinterpret_cast<const float4*>(b)[t];
    __half2 h0 = __floats2half2_rn((v.x - mu) * r * gv.x + bv.x,
                                   (v.y - mu) * r * gv.y + bv.y);
    __half2 h1 = __floats2half2_rn((v.z - mu) * r * gv.z + bv.z,
                                   (v.w - mu) * r * gv.w + bv.w);
    reinterpret_cast<__half2*>(out + (size_t)row * EMB)[2 * t]     = h0;
    reinterpret_cast<__half2*>(out + (size_t)row * EMB)[2 * t + 1] = h1;
}

// ---------------------------------------------------------------------------
// rowsum reduce: one warp per row, sums 256 partials.
// ---------------------------------------------------------------------------
__global__ void rowsum_kernel(const float* __restrict__ partial, float* __restrict__ rowsum) {
    const int row  = blockIdx.x * 8 + (threadIdx.x >> 5);
    const int lane = threadIdx.x & 31;
    const float* p = partial + (size_t)row * 256;
    float s = 0.f;
    #pragma unroll
    for (int i = 0; i < 8; i++) s += p[lane + i * 32];
    #pragma unroll
    for (int o = 16; o; o >>= 1) s += __shfl_xor_sync(0xffffffffu, s, o);
    if (lane == 0) rowsum[row] = s;
}

// ---------------------------------------------------------------------------
// List build: per row-tile, compact nonzero col-tile indices (ascending).
// ---------------------------------------------------------------------------
__global__ void listbuild_kernel(const int* __restrict__ flag,
                                 int* __restrict__ list, int* __restrict__ cnt) {
    const int i = blockIdx.x, lane = threadIdx.x;
    unsigned b0 = __ballot_sync(0xffffffffu, flag[i * 64 + lane] != 0);
    unsigned b1 = __ballot_sync(0xffffffffu, flag[i * 64 + 32 + lane] != 0);
    if (lane == 0) {
        int c = 0;
        for (int j = 0; j < 32; j++) if ((b0 >> j) & 1) list[i * 64 + c++] = j;
        for (int j = 0; j < 32; j++) if ((b1 >> j) & 1) list[i * 64 + c++] = j + 32;
        cnt[i] = c;
    }
}

// ---------------------------------------------------------------------------
// Transposes: out[Cc][R] = in[R][Cc]
// ---------------------------------------------------------------------------
__global__ void transpose_f2h_kernel(const float* __restrict__ in, __half* __restrict__ out,
                                     int R, int Cc) {
    __shared__ float tile[32][34];
    const int bx = blockIdx.x * 32, by = blockIdx.y * 32;
    int x = bx + threadIdx.x;
    #pragma unroll
    for (int i = 0; i < 32; i += 8)
        tile[threadIdx.y + i][threadIdx.x] = in[(size_t)(by + threadIdx.y + i) * Cc + x];
    __syncthreads();
    x = by + threadIdx.x;
    #pragma unroll
    for (int i = 0; i < 32; i += 8)
        out[(size_t)(bx + threadIdx.y + i) * R + x] = __float2half(tile[threadIdx.x][threadIdx.y + i]);
}
__global__ void transpose_h2h_kernel(const __half* __restrict__ in, __half* __restrict__ out,
                                     int R, int Cc) {
    __shared__ __half tile[32][34];
    const int bx = blockIdx.x * 32, by = blockIdx.y * 32;
    int x = bx + threadIdx.x;
    #pragma unroll
    for (int i = 0; i < 32; i += 8)
        tile[threadIdx.y + i][threadIdx.x] = in[(size_t)(by + threadIdx.y + i) * Cc + x];
    __syncthreads();
    x = by + threadIdx.x;
    #pragma unroll
    for (int i = 0; i < 32; i += 8)
        out[(size_t)(bx + threadIdx.y + i) * R + x] = tile[threadIdx.x][threadIdx.y + i];
}

// ===========================================================================
// Shared GEMM mainloop: CTA 128x128, 8 warps (warp tile 64x32), K-chunk 64,
// 3-stage cp.async, XOR-swizzled smem, ldmatrix.x4 A + B.
// ===========================================================================
#define GEMM_DECLS()                                                                 \
    const uint32_t sA = smem_u32(smem);                                              \
    const uint32_t sB = sA + 3u * 16384u;                                            \
    const int tid  = threadIdx.x;                                                    \
    const int lane = tid & 31, wid = tid >> 5;                                       \
    const int wm = wid & 1, wn = wid >> 1;                                           \
    const int q  = lane & 3, gr = lane >> 2;                                         \
    float acc[4][4][4];                                                              \
    _Pragma("unroll") for (int i = 0; i < 4; i++)                                    \
        _Pragma("unroll") for (int j = 0; j < 4; j++)                                \
            _Pragma("unroll") for (int c = 0; c < 4; c++) acc[i][j][c] = 0.f;        \
    const int a_row_in = ((lane >> 3) & 1) * 8 + (lane & 7);                         \
    const int a_gsel   = lane >> 4;                                                  \
    const int b_nt_ofs = (lane >> 4);                                                \
    const int b_kh     = (lane >> 3) & 1;                                            \
    const int b_row_in = lane & 7;

#define GEMM_COMPUTE_CHUNK(stg)                                                      \
    {                                                                                \
        const uint32_t aB = sA + (uint32_t)(stg) * 16384u;                           \
        const uint32_t bB = sB + (uint32_t)(stg) * 16384u;                           \
        _Pragma("unroll") for (int ks = 0; ks < 4; ks++) {                           \
            uint32_t a[4][4];                                                        \
            _Pragma("unroll") for (int mt = 0; mt < 4; mt++) {                       \
                const int row = wm * 64 + mt * 16 + a_row_in;                        \
                const uint32_t g = (uint32_t)((2 * ks + a_gsel) ^ (row & 7));        \
                ldsm_x4(a[mt], aB + (uint32_t)(row * 128) + (g << 4));               \
            }                                                                        \
            uint32_t bfr[2][4];                                                      \
            _Pragma("unroll") for (int p = 0; p < 2; p++) {                          \
                const int nt = 2 * p + b_nt_ofs;                                     \
                const int n  = wn * 32 + nt * 8 + b_row_in;                          \
                const uint32_t g = (uint32_t)((2 * ks + b_kh) ^ (n & 7));            \
                ldsm_x4(bfr[p], bB + (uint32_t)(n * 128) + (g << 4));                \
            }                                                                        \
            _Pragma("unroll") for (int mt = 0; mt < 4; mt++) {                       \
                mma_f16(acc[mt][0], a[mt], bfr[0][0], bfr[0][1]);                    \
                mma_f16(acc[mt][1], a[mt], bfr[0][2], bfr[0][3]);                    \
                mma_f16(acc[mt][2], a[mt], bfr[1][0], bfr[1][1]);                    \
                mma_f16(acc[mt][3], a[mt], bfr[1][2], bfr[1][3]);                    \
            }                                                                        \
        }                                                                            \
    }

#define GEMM_LOAD_CHUNK_BODY(A_, B_, K_, bm_, bn_, k0, stg)                          \
    _Pragma("unroll") for (int i = 0; i < 4; i++) {                                  \
        int idx = tid + i * 256;                                                     \
        int r = idx >> 3, cg = idx & 7;                                              \
        uint32_t off = (uint32_t)(r * 128 + ((cg ^ (r & 7)) << 4));                  \
        cp16(sA + (uint32_t)(stg) * 16384u + off,                                    \
             (A_) + (size_t)((bm_) + r) * (K_) + (k0) + cg * 8);                     \
    }                                                                                \
    _Pragma("unroll") for (int i = 0; i < 4; i++) {                                  \
        int idx = tid + i * 256;                                                     \
        int r = idx >> 3, cg = idx & 7;                                              \
        uint32_t off = (uint32_t)(r * 128 + ((cg ^ (r & 7)) << 4));                  \
        cp16(sB + (uint32_t)(stg) * 16384u + off,                                    \
             (B_) + (size_t)((bn_) + r) * (K_) + (k0) + cg * 8);                     \
    }                                                                                \
    asm volatile("cp.async.commit_group;");

// ---------------------------------------------------------------------------
// Symmetric QK kernel (tiles bj >= bi) + exp epilogue + partial row sums +
// nonzero-tile flags (based on STORED half bits).
// ---------------------------------------------------------------------------
__global__ __launch_bounds__(256, 2)
void qk_gemm(const __half* __restrict__ A,
             __half* __restrict__ Sh, const float* __restrict__ sp,
             float* __restrict__ partial, int* __restrict__ flag, float scale) {
    const int bi = blockIdx.y, bj = blockIdx.x;
    if (bj < bi) return;
    const int bm = bi * 128, bn = bj * 128;
    extern __shared__ char smem[];
    __shared__ int warpany[8];

    GEMM_DECLS()
    auto load_chunk = [&](int k0, int stg) { GEMM_LOAD_CHUNK_BODY(A, A, EMB, bm, bn, k0, stg) };
    const int nk = EMB / 64;
    load_chunk(0, 0);
    load_chunk(64, 1);
    for (int kc = 0; kc < nk; kc++) {
        if (kc == nk - 1) asm volatile("cp.async.wait_group %0;" :: "n"(0));
        else              asm volatile("cp.async.wait_group %0;" :: "n"(1));
        __syncthreads();
        GEMM_COMPUTE_CHUNK(kc % 3)
        if (kc + 2 < nk) load_chunk((kc + 2) * 64, (kc + 2) % 3);
    }

    // ---- normal epilogue (upper tile) ----
    uint32_t uany = 0;
    #pragma unroll
    for (int mt = 0; mt < 4; mt++) {
        #pragma unroll
        for (int half_ = 0; half_ < 2; half_++) {
            const int r = bm + wm * 64 + mt * 16 + gr + half_ * 8;
            const size_t ro = (size_t)r * NROWS;
            float rsum = 0.f;
            #pragma unroll
            for (int nt = 0; nt < 4; nt++) {
                const int c0 = bn + wn * 32 + nt * 8 + 2 * q;
                float v0 = acc[mt][nt][2 * half_ + 0];
                float v1 = acc[mt][nt][2 * half_ + 1];
                float2 a2 = *reinterpret_cast<const float2*>(sp + ro + c0);
                float e0 = __expf(v0 * scale + a2.x - EXP_SHIFT);
                float e1 = __expf(v1 * scale + a2.y - EXP_SHIFT);
                __half2 hh = __floats2half2_rn(e0, e1);
                *reinterpret_cast<__half2*>(Sh + ro + c0) = hh;
                uany |= reinterpret_cast<uint32_t&>(hh);
                rsum += e0 + e1;
            }
            rsum += __shfl_xor_sync(0xffffffffu, rsum, 1);
            rsum += __shfl_xor_sync(0xffffffffu, rsum, 2);
            if (q == 0)
                partial[(size_t)r * 256 + (size_t)(bj * 4 + wn)] = rsum;
        }
    }
    {
        int wa = __any_sync(0xffffffffu, uany != 0);
        if (lane == 0) warpany[wid] = wa;
        __syncthreads();
        if (tid == 0) {
            int f = 0;
            #pragma unroll
            for (int i = 0; i < 8; i++) f |= warpany[i];
            flag[bi * 64 + bj] = f;
        }
    }

    // ---- mirror epilogue (lower tile), bj > bi only ----
    if (bj > bi) {
        float* smT = reinterpret_cast<float*>(smem);   // 128 cols x stride 132 fp32
        __syncthreads();
        #pragma unroll
        for (int mt = 0; mt < 4; mt++) {
            #pragma unroll
            for (int half_ = 0; half_ < 2; half_++) {
                const int r = wm * 64 + mt * 16 + gr + half_ * 8;
                #pragma unroll
                for (int nt = 0; nt < 4; nt++) {
                    const int c = wn * 32 + nt * 8 + 2 * q;
                    smT[(size_t)c * 132 + r]       = acc[mt][nt][2 * half_ + 0];
                    smT[(size_t)(c + 1) * 132 + r] = acc[mt][nt][2 * half_ + 1];
                }
            }
        }
        __syncthreads();

        const int c  = tid >> 1;
        const int hf = tid & 1;
        const int cb = hf * 64;
        const size_t orow = (size_t)(bn + c) * NROWS + bm + cb;
        const float* srow = smT + (size_t)c * 132 + cb;
        const float* sprow = sp + orow;
        float s0 = 0.f, s1 = 0.f;
        uint32_t uany2 = 0;
        #pragma unroll
        for (int i = 0; i < 64; i += 8) {
            float4 f0 = *reinterpret_cast<const float4*>(srow + i);
            float4 f1 = *reinterpret_cast<const float4*>(srow + i + 4);
            float4 p0 = *reinterpret_cast<const float4*>(sprow + i);
            float4 p1 = *reinterpret_cast<const float4*>(sprow + i + 4);
            float e0 = __expf(f0.x * scale + p0.x - EXP_SHIFT);
            float e1 = __expf(f0.y * scale + p0.y - EXP_SHIFT);
            float e2 = __expf(f0.z * scale + p0.z - EXP_SHIFT);
            float e3 = __expf(f0.w * scale + p0.w - EXP_SHIFT);
            float e4 = __expf(f1.x * scale + p1.x - EXP_SHIFT);
            float e5 = __expf(f1.y * scale + p1.y - EXP_SHIFT);
            float e6 = __expf(f1.z * scale + p1.z - EXP_SHIFT);
            float e7 = __expf(f1.w * scale + p1.w - EXP_SHIFT);
            float sum8 = ((e0 + e1) + (e2 + e3)) + ((e4 + e5) + (e6 + e7));
            if (i < 32) s0 += sum8; else s1 += sum8;
            __half2 o[4];
            o[0] = __floats2half2_rn(e0, e1); o[1] = __floats2half2_rn(e2, e3);
            o[2] = __floats2half2_rn(e4, e5); o[3] = __floats2half2_rn(e6, e7);
            uint4 u4 = *reinterpret_cast<uint4*>(o);
            uany2 |= u4.x | u4.y | u4.z | u4.w;
            *reinterpret_cast<uint4*>(Sh + orow + i) = u4;
        }
        partial[(size_t)(bn + c) * 256 + (size_t)((bm >> 5) + hf * 2 + 0)] = s0;
        partial[(size_t)(bn + c) * 256 + (size_t)((bm >> 5) + hf * 2 + 1)] = s1;

        int wa2 = __any_sync(0xffffffffu, uany2 != 0);
        __syncthreads();
        if (lane == 0) warpany[wid] = wa2;
        __syncthreads();
        if (tid == 0) {
            int f = 0;
            #pragma unroll
            for (int i = 0; i < 8; i++) f |= warpany[i];
            flag[bj * 64 + bi] = f;
        }
    }
}

// ---------------------------------------------------------------------------
// AV GEMM with zero-tile skipping: iterates only k-chunks listed nonzero.
// x2 = acc / rowsum[r] + x
// ---------------------------------------------------------------------------
__global__ __launch_bounds__(256, 2)
void av_gemm(const __half* __restrict__ A, const __half* __restrict__ B,
             float* __restrict__ C, const float* __restrict__ xres,
             const float* __restrict__ rowsum,
             const int* __restrict__ list, const int* __restrict__ cnt) {
    extern __shared__ char smem[];
    __shared__ int slist[64];
    const int ti = blockIdx.y;
    const int bm = ti * 128, bn = blockIdx.x * 128;
    {
        const int t0 = threadIdx.x;
        if (t0 < 64) slist[t0] = list[ti * 64 + t0];
    }
    __syncthreads();
    const int nchunks = 2 * cnt[ti];

    GEMM_DECLS()
    auto load_chunk = [&](int ci, int stg) {
        const int k0 = slist[ci >> 1] * 128 + ((ci & 1) << 6);
        GEMM_LOAD_CHUNK_BODY(A, B, NROWS, bm, bn, k0, stg)
    };

    if (nchunks > 0) load_chunk(0, 0);
    if (nchunks > 1) load_chunk(1, 1);
    for (int ci = 0; ci < nchunks; ci++) {
        if (ci >= nchunks - 1) asm volatile("cp.async.wait_group %0;" :: "n"(0));
        else                   asm volatile("cp.async.wait_group %0;" :: "n"(1));
        __syncthreads();
        GEMM_COMPUTE_CHUNK(ci % 3)
        if (ci + 2 < nchunks) load_chunk(ci + 2, (ci + 2) % 3);
    }

    #pragma unroll
    for (int mt = 0; mt < 4; mt++) {
        #pragma unroll
        for (int half_ = 0; half_ < 2; half_++) {
            const int r = bm + wm * 64 + mt * 16 + gr + half_ * 8;
            const size_t ro = (size_t)r * EMB;
            const float inv = 1.0f / rowsum[r];
            #pragma unroll
            for (int nt = 0; nt < 4; nt++) {
                const int c0 = bn + wn * 32 + nt * 8 + 2 * q;
                float v0 = acc[mt][nt][2 * half_ + 0];
                float v1 = acc[mt][nt][2 * half_ + 1];
                float2 a2 = *reinterpret_cast<const float2*>(xres + ro + c0);
                *reinterpret_cast<float2*>(C + ro + c0) =
                    make_float2(v0 * inv + a2.x, v1 * inv + a2.y);
            }
        }
    }
}

// ---------------------------------------------------------------------------
// Generic GEMM (modes 2-3).
// MODE 2: C = half(relu(acc + bias))
// MODE 3: C = acc + bias + aux (f32)
// ---------------------------------------------------------------------------
template <int MODE>
__global__ __launch_bounds__(256, 2)
void mma_gemm(const __half* __restrict__ A, const __half* __restrict__ B,
              void* __restrict__ Cv, int M, int Nn, int K,
              const float* __restrict__ aux, const float* __restrict__ bias) {
    const int bm = blockIdx.y * 128, bn = blockIdx.x * 128;
    extern __shared__ char smem[];

    GEMM_DECLS()
    auto load_chunk = [&](int k0, int stg) { GEMM_LOAD_CHUNK_BODY(A, B, K, bm, bn, k0, stg) };
    const int nk = K / 64;
    load_chunk(0, 0);
    load_chunk(64, 1);
    for (int kc = 0; kc < nk; kc++) {
        if (kc == nk - 1) asm volatile("cp.async.wait_group %0;" :: "n"(0));
        else              asm volatile("cp.async.wait_group %0;" :: "n"(1));
        __syncthreads();
        GEMM_COMPUTE_CHUNK(kc % 3)
        if (kc + 2 < nk) load_chunk((kc + 2) * 64, (kc + 2) % 3);
    }

    #pragma unroll
    for (int mt = 0; mt < 4; mt++) {
        #pragma unroll
        for (int half_ = 0; half_ < 2; half_++) {
            const int r = bm + wm * 64 + mt * 16 + gr + half_ * 8;
            const size_t ro = (size_t)r * Nn;
            #pragma unroll
            for (int nt = 0; nt < 4; nt++) {
                const int c0 = bn + wn * 32 + nt * 8 + 2 * q;
                float v0 = acc[mt][nt][2 * half_ + 0];
                float v1 = acc[mt][nt][2 * half_ + 1];
                if (MODE == 2) {
                    float2 b2 = *reinterpret_cast<const float2*>(bias + c0);
                    *reinterpret_cast<__half2*>((__half*)Cv + ro + c0) =
                        __floats2half2_rn(fmaxf(v0 + b2.x, 0.f), fmaxf(v1 + b2.y, 0.f));
                } else {
                    float2 a2 = *reinterpret_cast<const float2*>(aux + ro + c0);
                    float2 b2 = *reinterpret_cast<const float2*>(bias + c0);
                    *reinterpret_cast<float2*>((float*)Cv + ro + c0) =
                        make_float2(v0 + b2.x + a2.x, v1 + b2.y + a2.y);
                }
            }
        }
    }
}

// ---------------------------------------------------------------------------
extern "C" void kernel_launch(void* const* d_in, const int* in_sizes, int n_in,
                              void* d_out, int out_size) {
    const float* x   = (const float*)d_in[0];
    const float* sp  = (const float*)d_in[2];
    const float* g1  = (const float*)d_in[3];
    const float* b1  = (const float*)d_in[4];
    const float* g2  = (const float*)d_in[5];
    const float* b2  = (const float*)d_in[6];
    const float* W1  = (const float*)d_in[7];
    const float* bb1 = (const float*)d_in[8];
    const float* W2  = (const float*)d_in[9];
    const float* bb2 = (const float*)d_in[10];
    float* out = (float*)d_out;

    __half *normx, *normxT, *Sh, *h, *t, *W1T, *W2T;
    float *x2, *partial, *rowsum;
    int *flag, *list, *cnt;
    cudaGetSymbolAddress((void**)&normx,   g_normx);
    cudaGetSymbolAddress((void**)&normxT,  g_normxT);
    cudaGetSymbolAddress((void**)&Sh,      g_Sh);
    cudaGetSymbolAddress((void**)&partial, g_partial);
    cudaGetSymbolAddress((void**)&rowsum,  g_rowsum);
    cudaGetSymbolAddress((void**)&flag,    g_flag);
    cudaGetSymbolAddress((void**)&list,    g_list);
    cudaGetSymbolAddress((void**)&cnt,     g_cnt);
    cudaGetSymbolAddress((void**)&x2,      g_x2);
    cudaGetSymbolAddress((void**)&h,       g_h);
    cudaGetSymbolAddress((void**)&t,       g_t);
    cudaGetSymbolAddress((void**)&W1T,     g_W1T);
    cudaGetSymbolAddress((void**)&W2T,     g_W2T);

    const int SMEM = 96 * 1024;
    cudaFuncSetAttribute(qk_gemm,     cudaFuncAttributeMaxDynamicSharedMemorySize, SMEM);
    cudaFuncSetAttribute(av_gemm,     cudaFuncAttributeMaxDynamicSharedMemorySize, SMEM);
    cudaFuncSetAttribute(mma_gemm<2>, cudaFuncAttributeMaxDynamicSharedMemorySize, SMEM);
    cudaFuncSetAttribute(mma_gemm<3>, cudaFuncAttributeMaxDynamicSharedMemorySize, SMEM);

    const float scale = 0.044194173824159216f;  // 1/sqrt(512)

    // launches 0-4 (keeps the QK^T GEMM at profile index 5)
    layernorm_kernel<<<NROWS / 2, 128>>>(x, g1, b1, normx);                       // 0
    layernorm_kernel<<<NROWS / 2, 128>>>(x + (size_t)(NROWS / 2) * EMB, g1, b1,
                                         normx + (size_t)(NROWS / 2) * EMB);      // 1
    transpose_h2h_kernel<<<dim3(EMB / 32, NROWS / 32), dim3(32, 8)>>>(
        normx, normxT, NROWS, EMB);                                               // 2
    transpose_f2h_kernel<<<dim3(DFF / 32, EMB / 32), dim3(32, 8)>>>(W1, W1T, EMB, DFF);  // 3
    transpose_f2h_kernel<<<dim3(EMB / 32, DFF / 32), dim3(32, 8)>>>(W2, W2T, DFF, EMB);  // 4

    // 5: symmetric QK: Sh = half(exp(S*scale + SP - 24)), partials + flags
    qk_gemm<<<dim3(NROWS / 128, NROWS / 128), 256, SMEM>>>(
        normx, Sh, sp, partial, flag, scale);

    // 6: rowsum = sum of partials
    rowsum_kernel<<<NROWS / 8, 256>>>(partial, rowsum);

    // 7: compact nonzero col-tile lists
    listbuild_kernel<<<NT64, 32>>>(flag, list, cnt);

    // 8: x2 = (expS @ norm_x) / rowsum + x, skipping all-zero Sh tiles
    av_gemm<<<dim3(EMB / 128, NROWS / 128), 256, SMEM>>>(
        Sh, normxT, x2, x, rowsum, list, cnt);

    // 9: h = LN(x2; g2, b2) -> half
    layernorm_kernel<<<NROWS, 128>>>(x2, g2, b2, h);

    // 10: t = relu(h @ W1 + bb1) -> half
    mma_gemm<2><<<dim3(DFF / 128, NROWS / 128), 256, SMEM>>>(
        h, W1T, t, NROWS, DFF, EMB, nullptr, bb1);

    // 11: out = t @ W2 + bb2 + x2
    mma_gemm<3><<<dim3(EMB / 128, NROWS / 128), 256, SMEM>>>(
        t, W2T, out, NROWS, EMB, DFF, x2, bb2);
}

// round 14
// speedup vs baseline: 1.7578x; 1.0059x over previous
#include <cuda_runtime.h>
#include <cuda_fp16.h>
#include <math.h>
#include <stdint.h>

#define NROWS 8192
#define EMB   512
#define DFF   2048
#define NT64  (NROWS / 128)   // 64 row/col tiles
#define NTRI  (NT64 * (NT64 + 1) / 2)   // 2080 upper-tri tiles

// ---------------- scratch (static device globals; no allocs) ----------------
static __device__ __half g_normx[NROWS * EMB];                 // 8 MB
static __device__ __half g_normxT[EMB * NROWS];                // 8 MB
static __device__ __half g_Sh[(size_t)NROWS * NROWS];          // 128 MB (exp scores, half)
static __device__ float  g_partial[(size_t)NROWS * 256];       // 8 MB
static __device__ float  g_rowsum[NROWS];                      // 32 KB
static __device__ int    g_flag[NT64 * NT64];                  // nonzero-tile flags
static __device__ int    g_list[NT64 * NT64];                  // compacted col-tile lists
static __device__ int    g_cnt[NT64];                          // list lengths
static __device__ float  g_x2[NROWS * EMB];                    // 16 MB
static __device__ __half g_h[NROWS * EMB];                     // 8 MB
static __device__ __half g_t[NROWS * DFF];                     // 32 MB
static __device__ __half g_W1T[(size_t)DFF * EMB];             // 2 MB
static __device__ __half g_W2T[(size_t)EMB * DFF];             // 2 MB

#define EXP_SHIFT 24.0f

// ---------------- helpers ----------------
__device__ __forceinline__ uint32_t smem_u32(const void* p) {
    uint32_t a;
    asm("{ .reg .u64 t; cvta.to.shared.u64 t, %1; cvt.u32.u64 %0, t; }" : "=r"(a) : "l"(p));
    return a;
}
__device__ __forceinline__ void cp16(uint32_t dst, const void* src) {
    asm volatile("cp.async.cg.shared.global [%0], [%1], 16;" :: "r"(dst), "l"(src));
}
__device__ __forceinline__ void ldsm_x4(uint32_t a[4], uint32_t addr) {
    asm volatile("ldmatrix.sync.aligned.m8n8.x4.shared.b16 {%0,%1,%2,%3}, [%4];"
                 : "=r"(a[0]), "=r"(a[1]), "=r"(a[2]), "=r"(a[3]) : "r"(addr));
}
__device__ __forceinline__ void mma_f16(float c[4], const uint32_t a[4], uint32_t b0, uint32_t b1) {
    asm volatile(
        "mma.sync.aligned.m16n8k16.row.col.f32.f16.f16.f32 "
        "{%0,%1,%2,%3}, {%4,%5,%6,%7}, {%8,%9}, {%0,%1,%2,%3};"
        : "+f"(c[0]), "+f"(c[1]), "+f"(c[2]), "+f"(c[3])
        : "r"(a[0]), "r"(a[1]), "r"(a[2]), "r"(a[3]), "r"(b0), "r"(b1));
}

// ---------------------------------------------------------------------------
// LayerNorm: one block per row, 128 threads. fp32 in, half out.
// ---------------------------------------------------------------------------
__global__ void layernorm_kernel(const float* __restrict__ x,
                                 const float* __restrict__ g,
                                 const float* __restrict__ b,
                                 __half* __restrict__ out) {
    const int row = blockIdx.x;
    const int t = threadIdx.x;
    float4 v = reinterpret_cast<const float4*>(x + (size_t)row * EMB)[t];

    float s  = v.x + v.y + v.z + v.w;
    float ss = v.x * v.x + v.y * v.y + v.z * v.z + v.w * v.w;

    __shared__ float red_s[4], red_ss[4];
    #pragma unroll
    for (int o = 16; o; o >>= 1) {
        s  += __shfl_xor_sync(0xffffffffu, s,  o);
        ss += __shfl_xor_sync(0xffffffffu, ss, o);
    }
    if ((t & 31) == 0) { red_s[t >> 5] = s; red_ss[t >> 5] = ss; }
    __syncthreads();
    s  = red_s[0]  + red_s[1]  + red_s[2]  + red_s[3];
    ss = red_ss[0] + red_ss[1] + red_ss[2] + red_ss[3];

    const float mu  = s * (1.0f / EMB);
    const float var = ss * (1.0f / EMB) - mu * mu;
    const float r   = rsqrtf(var + 1e-5f);

    float4 gv = reinterpret_cast<const float4*>(g)[t];
    float4 bv = reinterpret_cast<const float4*>(b)[t];
    __half2 h0 = __floats2half2_rn((v.x - mu) * r * gv.x + bv.x,
                                   (v.y - mu) * r * gv.y + bv.y);
    __half2 h1 = __floats2half2_rn((v.z - mu) * r * gv.z + bv.z,
                                   (v.w - mu) * r * gv.w + bv.w);
    reinterpret_cast<__half2*>(out + (size_t)row * EMB)[2 * t]     = h0;
    reinterpret_cast<__half2*>(out + (size_t)row * EMB)[2 * t + 1] = h1;
}

// ---------------------------------------------------------------------------
// rowsum reduce: one warp per row, sums 256 partials.
// ---------------------------------------------------------------------------
__global__ void rowsum_kernel(const float* __restrict__ partial, float* __restrict__ rowsum) {
    const int row  = blockIdx.x * 8 + (threadIdx.x >> 5);
    const int lane = threadIdx.x & 31;
    const float* p = partial + (size_t)row * 256;
    float s = 0.f;
    #pragma unroll
    for (int i = 0; i < 8; i++) s += p[lane + i * 32];
    #pragma unroll
    for (int o = 16; o; o >>= 1) s += __shfl_xor_sync(0xffffffffu, s, o);
    if (lane == 0) rowsum[row] = s;
}

// ---------------------------------------------------------------------------
// List build: per row-tile, compact nonzero col-tile indices (ascending).
// ---------------------------------------------------------------------------
__global__ void listbuild_kernel(const int* __restrict__ flag,
                                 int* __restrict__ list, int* __restrict__ cnt) {
    const int i = blockIdx.x, lane = threadIdx.x;
    unsigned b0 = __ballot_sync(0xffffffffu, flag[i * 64 + lane] != 0);
    unsigned b1 = __ballot_sync(0xffffffffu, flag[i * 64 + 32 + lane] != 0);
    if (lane == 0) {
        int c = 0;
        for (int j = 0; j < 32; j++) if ((b0 >> j) & 1) list[i * 64 + c++] = j;
        for (int j = 0; j < 32; j++) if ((b1 >> j) & 1) list[i * 64 + c++] = j + 32;
        cnt[i] = c;
    }
}

// ---------------------------------------------------------------------------
// Transposes: out[Cc][R] = in[R][Cc]
// ---------------------------------------------------------------------------
__global__ void transpose_f2h_kernel(const float* __restrict__ in, __half* __restrict__ out,
                                     int R, int Cc) {
    __shared__ float tile[32][34];
    const int bx = blockIdx.x * 32, by = blockIdx.y * 32;
    int x = bx + threadIdx.x;
    #pragma unroll
    for (int i = 0; i < 32; i += 8)
        tile[threadIdx.y + i][threadIdx.x] = in[(size_t)(by + threadIdx.y + i) * Cc + x];
    __syncthreads();
    x = by + threadIdx.x;
    #pragma unroll
    for (int i = 0; i < 32; i += 8)
        out[(size_t)(bx + threadIdx.y + i) * R + x] = __float2half(tile[threadIdx.x][threadIdx.y + i]);
}
__global__ void transpose_h2h_kernel(const __half* __restrict__ in, __half* __restrict__ out,
                                     int R, int Cc) {
    __shared__ __half tile[32][34];
    const int bx = blockIdx.x * 32, by = blockIdx.y * 32;
    int x = bx + threadIdx.x;
    #pragma unroll
    for (int i = 0; i < 32; i += 8)
        tile[threadIdx.y + i][threadIdx.x] = in[(size_t)(by + threadIdx.y + i) * Cc + x];
    __syncthreads();
    x = by + threadIdx.x;
    #pragma unroll
    for (int i = 0; i < 32; i += 8)
        out[(size_t)(bx + threadIdx.y + i) * R + x] = tile[threadIdx.x][threadIdx.y + i];
}

// ===========================================================================
// Shared GEMM mainloop: CTA 128x128, 8 warps (warp tile 64x32), K-chunk 64,
// 3-stage cp.async, XOR-swizzled smem, ldmatrix.x4 A + B.
// ===========================================================================
#define GEMM_DECLS()                                                                 \
    const uint32_t sA = smem_u32(smem);                                              \
    const uint32_t sB = sA + 3u * 16384u;                                            \
    const int tid  = threadIdx.x;                                                    \
    const int lane = tid & 31, wid = tid >> 5;                                       \
    const int wm = wid & 1, wn = wid >> 1;                                           \
    const int q  = lane & 3, gr = lane >> 2;                                         \
    float acc[4][4][4];                                                              \
    _Pragma("unroll") for (int i = 0; i < 4; i++)                                    \
        _Pragma("unroll") for (int j = 0; j < 4; j++)                                \
            _Pragma("unroll") for (int c = 0; c < 4; c++) acc[i][j][c] = 0.f;        \
    const int a_row_in = ((lane >> 3) & 1) * 8 + (lane & 7);                         \
    const int a_gsel   = lane >> 4;                                                  \
    const int b_nt_ofs = (lane >> 4);                                                \
    const int b_kh     = (lane >> 3) & 1;                                            \
    const int b_row_in = lane & 7;

#define GEMM_COMPUTE_CHUNK(stg)                                                      \
    {                                                                                \
        const uint32_t aB = sA + (uint32_t)(stg) * 16384u;                           \
        const uint32_t bB = sB + (uint32_t)(stg) * 16384u;                           \
        _Pragma("unroll") for (int ks = 0; ks < 4; ks++) {                           \
            uint32_t a[4][4];                                                        \
            _Pragma("unroll") for (int mt = 0; mt < 4; mt++) {                       \
                const int row = wm * 64 + mt * 16 + a_row_in;                        \
                const uint32_t g = (uint32_t)((2 * ks + a_gsel) ^ (row & 7));        \
                ldsm_x4(a[mt], aB + (uint32_t)(row * 128) + (g << 4));               \
            }                                                                        \
            uint32_t bfr[2][4];                                                      \
            _Pragma("unroll") for (int p = 0; p < 2; p++) {                          \
                const int nt = 2 * p + b_nt_ofs;                                     \
                const int n  = wn * 32 + nt * 8 + b_row_in;                          \
                const uint32_t g = (uint32_t)((2 * ks + b_kh) ^ (n & 7));            \
                ldsm_x4(bfr[p], bB + (uint32_t)(n * 128) + (g << 4));                \
            }                                                                        \
            _Pragma("unroll") for (int mt = 0; mt < 4; mt++) {                       \
                mma_f16(acc[mt][0], a[mt], bfr[0][0], bfr[0][1]);                    \
                mma_f16(acc[mt][1], a[mt], bfr[0][2], bfr[0][3]);                    \
                mma_f16(acc[mt][2], a[mt], bfr[1][0], bfr[1][1]);                    \
                mma_f16(acc[mt][3], a[mt], bfr[1][2], bfr[1][3]);                    \
            }                                                                        \
        }                                                                            \
    }

#define GEMM_LOAD_CHUNK_BODY(A_, B_, K_, bm_, bn_, k0, stg)                          \
    _Pragma("unroll") for (int i = 0; i < 4; i++) {                                  \
        int idx = tid + i * 256;                                                     \
        int r = idx >> 3, cg = idx & 7;                                              \
        uint32_t off = (uint32_t)(r * 128 + ((cg ^ (r & 7)) << 4));                  \
        cp16(sA + (uint32_t)(stg) * 16384u + off,                                    \
             (A_) + (size_t)((bm_) + r) * (K_) + (k0) + cg * 8);                     \
    }                                                                                \
    _Pragma("unroll") for (int i = 0; i < 4; i++) {                                  \
        int idx = tid + i * 256;                                                     \
        int r = idx >> 3, cg = idx & 7;                                              \
        uint32_t off = (uint32_t)(r * 128 + ((cg ^ (r & 7)) << 4));                  \
        cp16(sB + (uint32_t)(stg) * 16384u + off,                                    \
             (B_) + (size_t)((bn_) + r) * (K_) + (k0) + cg * 8);                     \
    }                                                                                \
    asm volatile("cp.async.commit_group;");

// ---------------------------------------------------------------------------
// Symmetric QK kernel, COMPACT 1-D triangular grid (2080 CTAs, bj >= bi).
// exp epilogue + partial row sums + nonzero-tile flags; mirror epilogue
// writes the (bj,bi) tile.
// ---------------------------------------------------------------------------
__global__ __launch_bounds__(256, 2)
void qk_gemm(const __half* __restrict__ A,
             __half* __restrict__ Sh, const float* __restrict__ sp,
             float* __restrict__ partial, int* __restrict__ flag, float scale) {
    // invert u -> (bi, bj): off(b) = 64b - b(b-1)/2
    const int u = blockIdx.x;
    int bi = (int)((129.0f - sqrtf(16641.0f - 8.0f * (float)u)) * 0.5f);
    while (64 * bi - (bi * (bi - 1)) / 2 > u) bi--;
    while (64 * (bi + 1) - ((bi + 1) * bi) / 2 <= u) bi++;
    const int bj = bi + (u - (64 * bi - (bi * (bi - 1)) / 2));
    const int bm = bi * 128, bn = bj * 128;

    extern __shared__ char smem[];
    __shared__ int warpany[8];

    GEMM_DECLS()
    auto load_chunk = [&](int k0, int stg) { GEMM_LOAD_CHUNK_BODY(A, A, EMB, bm, bn, k0, stg) };
    const int nk = EMB / 64;
    load_chunk(0, 0);
    load_chunk(64, 1);
    for (int kc = 0; kc < nk; kc++) {
        if (kc == nk - 1) asm volatile("cp.async.wait_group %0;" :: "n"(0));
        else              asm volatile("cp.async.wait_group %0;" :: "n"(1));
        __syncthreads();
        GEMM_COMPUTE_CHUNK(kc % 3)
        if (kc + 2 < nk) load_chunk((kc + 2) * 64, (kc + 2) % 3);
    }

    // ---- normal epilogue (upper tile) ----
    uint32_t uany = 0;
    #pragma unroll
    for (int mt = 0; mt < 4; mt++) {
        #pragma unroll
        for (int half_ = 0; half_ < 2; half_++) {
            const int r = bm + wm * 64 + mt * 16 + gr + half_ * 8;
            const size_t ro = (size_t)r * NROWS;
            float rsum = 0.f;
            #pragma unroll
            for (int nt = 0; nt < 4; nt++) {
                const int c0 = bn + wn * 32 + nt * 8 + 2 * q;
                float v0 = acc[mt][nt][2 * half_ + 0];
                float v1 = acc[mt][nt][2 * half_ + 1];
                float2 a2 = *reinterpret_cast<const float2*>(sp + ro + c0);
                float e0 = __expf(v0 * scale + a2.x - EXP_SHIFT);
                float e1 = __expf(v1 * scale + a2.y - EXP_SHIFT);
                __half2 hh = __floats2half2_rn(e0, e1);
                *reinterpret_cast<__half2*>(Sh + ro + c0) = hh;
                uany |= reinterpret_cast<uint32_t&>(hh);
                rsum += e0 + e1;
            }
            rsum += __shfl_xor_sync(0xffffffffu, rsum, 1);
            rsum += __shfl_xor_sync(0xffffffffu, rsum, 2);
            if (q == 0)
                partial[(size_t)r * 256 + (size_t)(bj * 4 + wn)] = rsum;
        }
    }
    {
        int wa = __any_sync(0xffffffffu, uany != 0);
        if (lane == 0) warpany[wid] = wa;
        __syncthreads();
        if (tid == 0) {
            int f = 0;
            #pragma unroll
            for (int i = 0; i < 8; i++) f |= warpany[i];
            flag[bi * 64 + bj] = f;
        }
    }

    // ---- mirror epilogue (lower tile), bj > bi only ----
    if (bj > bi) {
        float* smT = reinterpret_cast<float*>(smem);   // 128 cols x stride 132 fp32
        __syncthreads();
        #pragma unroll
        for (int mt = 0; mt < 4; mt++) {
            #pragma unroll
            for (int half_ = 0; half_ < 2; half_++) {
                const int r = wm * 64 + mt * 16 + gr + half_ * 8;
                #pragma unroll
                for (int nt = 0; nt < 4; nt++) {
                    const int c = wn * 32 + nt * 8 + 2 * q;
                    smT[(size_t)c * 132 + r]       = acc[mt][nt][2 * half_ + 0];
                    smT[(size_t)(c + 1) * 132 + r] = acc[mt][nt][2 * half_ + 1];
                }
            }
        }
        __syncthreads();

        const int c  = tid >> 1;
        const int hf = tid & 1;
        const int cb = hf * 64;
        const size_t orow = (size_t)(bn + c) * NROWS + bm + cb;
        const float* srow = smT + (size_t)c * 132 + cb;
        const float* sprow = sp + orow;
        float s0 = 0.f, s1 = 0.f;
        uint32_t uany2 = 0;
        #pragma unroll
        for (int i = 0; i < 64; i += 8) {
            float4 f0 = *reinterpret_cast<const float4*>(srow + i);
            float4 f1 = *reinterpret_cast<const float4*>(srow + i + 4);
            float4 p0 = *reinterpret_cast<const float4*>(sprow + i);
            float4 p1 = *reinterpret_cast<const float4*>(sprow + i + 4);
            float e0 = __expf(f0.x * scale + p0.x - EXP_SHIFT);
            float e1 = __expf(f0.y * scale + p0.y - EXP_SHIFT);
            float e2 = __expf(f0.z * scale + p0.z - EXP_SHIFT);
            float e3 = __expf(f0.w * scale + p0.w - EXP_SHIFT);
            float e4 = __expf(f1.x * scale + p1.x - EXP_SHIFT);
            float e5 = __expf(f1.y * scale + p1.y - EXP_SHIFT);
            float e6 = __expf(f1.z * scale + p1.z - EXP_SHIFT);
            float e7 = __expf(f1.w * scale + p1.w - EXP_SHIFT);
            float sum8 = ((e0 + e1) + (e2 + e3)) + ((e4 + e5) + (e6 + e7));
            if (i < 32) s0 += sum8; else s1 += sum8;
            __half2 o[4];
            o[0] = __floats2half2_rn(e0, e1); o[1] = __floats2half2_rn(e2, e3);
            o[2] = __floats2half2_rn(e4, e5); o[3] = __floats2half2_rn(e6, e7);
            uint4 u4 = *reinterpret_cast<uint4*>(o);
            uany2 |= u4.x | u4.y | u4.z | u4.w;
            *reinterpret_cast<uint4*>(Sh + orow + i) = u4;
        }
        partial[(size_t)(bn + c) * 256 + (size_t)((bm >> 5) + hf * 2 + 0)] = s0;
        partial[(size_t)(bn + c) * 256 + (size_t)((bm >> 5) + hf * 2 + 1)] = s1;

        int wa2 = __any_sync(0xffffffffu, uany2 != 0);
        __syncthreads();
        if (lane == 0) warpany[wid] = wa2;
        __syncthreads();
        if (tid == 0) {
            int f = 0;
            #pragma unroll
            for (int i = 0; i < 8; i++) f |= warpany[i];
            flag[bj * 64 + bi] = f;
        }
    }
}

// ---------------------------------------------------------------------------
// AV GEMM with zero-tile skipping: iterates only k-chunks listed nonzero.
// x2 = acc / rowsum[r] + x
// ---------------------------------------------------------------------------
__global__ __launch_bounds__(256, 2)
void av_gemm(const __half* __restrict__ A, const __half* __restrict__ B,
             float* __restrict__ C, const float* __restrict__ xres,
             const float* __restrict__ rowsum,
             const int* __restrict__ list, const int* __restrict__ cnt) {
    extern __shared__ char smem[];
    __shared__ int slist[64];
    const int ti = blockIdx.y;
    const int bm = ti * 128, bn = blockIdx.x * 128;
    {
        const int t0 = threadIdx.x;
        if (t0 < 64) slist[t0] = list[ti * 64 + t0];
    }
    __syncthreads();
    const int nchunks = 2 * cnt[ti];

    GEMM_DECLS()
    auto load_chunk = [&](int ci, int stg) {
        const int k0 = slist[ci >> 1] * 128 + ((ci & 1) << 6);
        GEMM_LOAD_CHUNK_BODY(A, B, NROWS, bm, bn, k0, stg)
    };

    if (nchunks > 0) load_chunk(0, 0);
    if (nchunks > 1) load_chunk(1, 1);
    for (int ci = 0; ci < nchunks; ci++) {
        if (ci >= nchunks - 1) asm volatile("cp.async.wait_group %0;" :: "n"(0));
        else                   asm volatile("cp.async.wait_group %0;" :: "n"(1));
        __syncthreads();
        GEMM_COMPUTE_CHUNK(ci % 3)
        if (ci + 2 < nchunks) load_chunk(ci + 2, (ci + 2) % 3);
    }

    #pragma unroll
    for (int mt = 0; mt < 4; mt++) {
        #pragma unroll
        for (int half_ = 0; half_ < 2; half_++) {
            const int r = bm + wm * 64 + mt * 16 + gr + half_ * 8;
            const size_t ro = (size_t)r * EMB;
            const float inv = 1.0f / rowsum[r];
            #pragma unroll
            for (int nt = 0; nt < 4; nt++) {
                const int c0 = bn + wn * 32 + nt * 8 + 2 * q;
                float v0 = acc[mt][nt][2 * half_ + 0];
                float v1 = acc[mt][nt][2 * half_ + 1];
                float2 a2 = *reinterpret_cast<const float2*>(xres + ro + c0);
                *reinterpret_cast<float2*>(C + ro + c0) =
                    make_float2(v0 * inv + a2.x, v1 * inv + a2.y);
            }
        }
    }
}

// ---------------------------------------------------------------------------
// Generic GEMM (modes 2-3).
// MODE 2: C = half(relu(acc + bias))
// MODE 3: C = acc + bias + aux (f32)
// ---------------------------------------------------------------------------
template <int MODE>
__global__ __launch_bounds__(256, 2)
void mma_gemm(const __half* __restrict__ A, const __half* __restrict__ B,
              void* __restrict__ Cv, int M, int Nn, int K,
              const float* __restrict__ aux, const float* __restrict__ bias) {
    const int bm = blockIdx.y * 128, bn = blockIdx.x * 128;
    extern __shared__ char smem[];

    GEMM_DECLS()
    auto load_chunk = [&](int k0, int stg) { GEMM_LOAD_CHUNK_BODY(A, B, K, bm, bn, k0, stg) };
    const int nk = K / 64;
    load_chunk(0, 0);
    load_chunk(64, 1);
    for (int kc = 0; kc < nk; kc++) {
        if (kc == nk - 1) asm volatile("cp.async.wait_group %0;" :: "n"(0));
        else              asm volatile("cp.async.wait_group %0;" :: "n"(1));
        __syncthreads();
        GEMM_COMPUTE_CHUNK(kc % 3)
        if (kc + 2 < nk) load_chunk((kc + 2) * 64, (kc + 2) % 3);
    }

    #pragma unroll
    for (int mt = 0; mt < 4; mt++) {
        #pragma unroll
        for (int half_ = 0; half_ < 2; half_++) {
            const int r = bm + wm * 64 + mt * 16 + gr + half_ * 8;
            const size_t ro = (size_t)r * Nn;
            #pragma unroll
            for (int nt = 0; nt < 4; nt++) {
                const int c0 = bn + wn * 32 + nt * 8 + 2 * q;
                float v0 = acc[mt][nt][2 * half_ + 0];
                float v1 = acc[mt][nt][2 * half_ + 1];
                if (MODE == 2) {
                    float2 b2 = *reinterpret_cast<const float2*>(bias + c0);
                    *reinterpret_cast<__half2*>((__half*)Cv + ro + c0) =
                        __floats2half2_rn(fmaxf(v0 + b2.x, 0.f), fmaxf(v1 + b2.y, 0.f));
                } else {
                    float2 a2 = *reinterpret_cast<const float2*>(aux + ro + c0);
                    float2 b2 = *reinterpret_cast<const float2*>(bias + c0);
                    *reinterpret_cast<float2*>((float*)Cv + ro + c0) =
                        make_float2(v0 + b2.x + a2.x, v1 + b2.y + a2.y);
                }
            }
        }
    }
}

// ---------------------------------------------------------------------------
extern "C" void kernel_launch(void* const* d_in, const int* in_sizes, int n_in,
                              void* d_out, int out_size) {
    const float* x   = (const float*)d_in[0];
    const float* sp  = (const float*)d_in[2];
    const float* g1  = (const float*)d_in[3];
    const float* b1  = (const float*)d_in[4];
    const float* g2  = (const float*)d_in[5];
    const float* b2  = (const float*)d_in[6];
    const float* W1  = (const float*)d_in[7];
    const float* bb1 = (const float*)d_in[8];
    const float* W2  = (const float*)d_in[9];
    const float* bb2 = (const float*)d_in[10];
    float* out = (float*)d_out;

    __half *normx, *normxT, *Sh, *h, *t, *W1T, *W2T;
    float *x2, *partial, *rowsum;
    int *flag, *list, *cnt;
    cudaGetSymbolAddress((void**)&normx,   g_normx);
    cudaGetSymbolAddress((void**)&normxT,  g_normxT);
    cudaGetSymbolAddress((void**)&Sh,      g_Sh);
    cudaGetSymbolAddress((void**)&partial, g_partial);
    cudaGetSymbolAddress((void**)&rowsum,  g_rowsum);
    cudaGetSymbolAddress((void**)&flag,    g_flag);
    cudaGetSymbolAddress((void**)&list,    g_list);
    cudaGetSymbolAddress((void**)&cnt,     g_cnt);
    cudaGetSymbolAddress((void**)&x2,      g_x2);
    cudaGetSymbolAddress((void**)&h,       g_h);
    cudaGetSymbolAddress((void**)&t,       g_t);
    cudaGetSymbolAddress((void**)&W1T,     g_W1T);
    cudaGetSymbolAddress((void**)&W2T,     g_W2T);

    const int SMEM = 96 * 1024;
    cudaFuncSetAttribute(qk_gemm,     cudaFuncAttributeMaxDynamicSharedMemorySize, SMEM);
    cudaFuncSetAttribute(av_gemm,     cudaFuncAttributeMaxDynamicSharedMemorySize, SMEM);
    cudaFuncSetAttribute(mma_gemm<2>, cudaFuncAttributeMaxDynamicSharedMemorySize, SMEM);
    cudaFuncSetAttribute(mma_gemm<3>, cudaFuncAttributeMaxDynamicSharedMemorySize, SMEM);

    const float scale = 0.044194173824159216f;  // 1/sqrt(512)

    // 0-2: LN + normx^T (QK deps only) — puts qk_gemm at launch index 3
    layernorm_kernel<<<NROWS / 2, 128>>>(x, g1, b1, normx);                       // 0
    layernorm_kernel<<<NROWS / 2, 128>>>(x + (size_t)(NROWS / 2) * EMB, g1, b1,
                                         normx + (size_t)(NROWS / 2) * EMB);      // 1
    transpose_h2h_kernel<<<dim3(EMB / 32, NROWS / 32), dim3(32, 8)>>>(
        normx, normxT, NROWS, EMB);                                               // 2

    // 3: symmetric QK, compact triangular grid (2080 CTAs)
    qk_gemm<<<NTRI, 256, SMEM>>>(normx, Sh, sp, partial, flag, scale);            // 3

    // 4-5: weight transposes (independent; overlap QK tail)
    transpose_f2h_kernel<<<dim3(DFF / 32, EMB / 32), dim3(32, 8)>>>(W1, W1T, EMB, DFF);  // 4
    transpose_f2h_kernel<<<dim3(EMB / 32, DFF / 32), dim3(32, 8)>>>(W2, W2T, DFF, EMB);  // 5

    // 6: rowsum = sum of partials
    rowsum_kernel<<<NROWS / 8, 256>>>(partial, rowsum);                           // 6

    // 7: compact nonzero col-tile lists
    listbuild_kernel<<<NT64, 32>>>(flag, list, cnt);                              // 7

    // 8: x2 = (expS @ norm_x) / rowsum + x, skipping all-zero Sh tiles
    av_gemm<<<dim3(EMB / 128, NROWS / 128), 256, SMEM>>>(
        Sh, normxT, x2, x, rowsum, list, cnt);                                    // 8

    // 9: h = LN(x2; g2, b2) -> half
    layernorm_kernel<<<NROWS, 128>>>(x2, g2, b2, h);                              // 9

    // 10: t = relu(h @ W1 + bb1) -> half
    mma_gemm<2><<<dim3(DFF / 128, NROWS / 128), 256, SMEM>>>(
        h, W1T, t, NROWS, DFF, EMB, nullptr, bb1);                                // 10

    // 11: out = t @ W2 + bb2 + x2
    mma_gemm<3><<<dim3(EMB / 128, NROWS / 128), 256, SMEM>>>(
        t, W2T, out, NROWS, EMB, DFF, x2, bb2);                                   // 11
}

// round 17
// speedup vs baseline: 1.7679x; 1.0057x over previous
#include <cuda_runtime.h>
#include <cuda_fp16.h>
#include <math.h>
#include <stdint.h>

#define NROWS 8192
#define EMB   512
#define DFF   2048
#define NT64  (NROWS / 128)   // 64 row/col tiles
#define NTRI  (NT64 * (NT64 + 1) / 2)   // 2080 upper-tri tiles

// ---------------- scratch (static device globals; no allocs) ----------------
static __device__ __half g_normx[NROWS * EMB];                 // 8 MB
static __device__ __half g_normxT[EMB * NROWS];                // 8 MB
static __device__ __half g_Sh[(size_t)NROWS * NROWS];          // 128 MB (exp scores, half)
static __device__ float  g_partial[(size_t)NROWS * 256];       // 8 MB
static __device__ float  g_rowsum[NROWS];                      // 32 KB
static __device__ int    g_flag[NT64 * NT64];                  // nonzero-tile flags
static __device__ int    g_list[NT64 * NT64];                  // compacted col-tile lists
static __device__ int    g_cnt[NT64];                          // list lengths
static __device__ float  g_x2[NROWS * EMB];                    // 16 MB
static __device__ __half g_h[NROWS * EMB];                     // 8 MB
static __device__ __half g_t[NROWS * DFF];                     // 32 MB
static __device__ __half g_W1T[(size_t)DFF * EMB];             // 2 MB
static __device__ __half g_W2T[(size_t)EMB * DFF];             // 2 MB

#define EXP_SHIFT 24.0f

// ---------------- helpers ----------------
__device__ __forceinline__ uint32_t smem_u32(const void* p) {
    uint32_t a;
    asm("{ .reg .u64 t; cvta.to.shared.u64 t, %1; cvt.u32.u64 %0, t; }" : "=r"(a) : "l"(p));
    return a;
}
__device__ __forceinline__ void cp16(uint32_t dst, const void* src) {
    asm volatile("cp.async.cg.shared.global [%0], [%1], 16;" :: "r"(dst), "l"(src));
}
__device__ __forceinline__ void ldsm_x4(uint32_t a[4], uint32_t addr) {
    asm volatile("ldmatrix.sync.aligned.m8n8.x4.shared.b16 {%0,%1,%2,%3}, [%4];"
                 : "=r"(a[0]), "=r"(a[1]), "=r"(a[2]), "=r"(a[3]) : "r"(addr));
}
__device__ __forceinline__ void mma_f16(float c[4], const uint32_t a[4], uint32_t b0, uint32_t b1) {
    asm volatile(
        "mma.sync.aligned.m16n8k16.row.col.f32.f16.f16.f32 "
        "{%0,%1,%2,%3}, {%4,%5,%6,%7}, {%8,%9}, {%0,%1,%2,%3};"
        : "+f"(c[0]), "+f"(c[1]), "+f"(c[2]), "+f"(c[3])
        : "r"(a[0]), "r"(a[1]), "r"(a[2]), "r"(a[3]), "r"(b0), "r"(b1));
}

// ---------------------------------------------------------------------------
// LayerNorm: one block per row, 128 threads. fp32 in, half out.
// ---------------------------------------------------------------------------
__global__ void layernorm_kernel(const float* __restrict__ x,
                                 const float* __restrict__ g,
                                 const float* __restrict__ b,
                                 __half* __restrict__ out) {
    const int row = blockIdx.x;
    const int t = threadIdx.x;
    float4 v = reinterpret_cast<const float4*>(x + (size_t)row * EMB)[t];

    float s  = v.x + v.y + v.z + v.w;
    float ss = v.x * v.x + v.y * v.y + v.z * v.z + v.w * v.w;

    __shared__ float red_s[4], red_ss[4];
    #pragma unroll
    for (int o = 16; o; o >>= 1) {
        s  += __shfl_xor_sync(0xffffffffu, s,  o);
        ss += __shfl_xor_sync(0xffffffffu, ss, o);
    }
    if ((t & 31) == 0) { red_s[t >> 5] = s; red_ss[t >> 5] = ss; }
    __syncthreads();
    s  = red_s[0]  + red_s[1]  + red_s[2]  + red_s[3];
    ss = red_ss[0] + red_ss[1] + red_ss[2] + red_ss[3];

    const float mu  = s * (1.0f / EMB);
    const float var = ss * (1.0f / EMB) - mu * mu;
    const float r   = rsqrtf(var + 1e-5f);

    float4 gv = reinterpret_cast<const float4*>(g)[t];
    float4 bv = reinterpret_cast<const float4*>(b)[t];
    __half2 h0 = __floats2half2_rn((v.x - mu) * r * gv.x + bv.x,
                                   (v.y - mu) * r * gv.y + bv.y);
    __half2 h1 = __floats2half2_rn((v.z - mu) * r * gv.z + bv.z,
                                   (v.w - mu) * r * gv.w + bv.w);
    reinterpret_cast<__half2*>(out + (size_t)row * EMB)[2 * t]     = h0;
    reinterpret_cast<__half2*>(out + (size_t)row * EMB)[2 * t + 1] = h1;
}

// ---------------------------------------------------------------------------
// rowsum reduce: one warp per row, sums 256 partials.
// ---------------------------------------------------------------------------
__global__ void rowsum_kernel(const float* __restrict__ partial, float* __restrict__ rowsum) {
    const int row  = blockIdx.x * 8 + (threadIdx.x >> 5);
    const int lane = threadIdx.x & 31;
    const float* p = partial + (size_t)row * 256;
    float s = 0.f;
    #pragma unroll
    for (int i = 0; i < 8; i++) s += p[lane + i * 32];
    #pragma unroll
    for (int o = 16; o; o >>= 1) s += __shfl_xor_sync(0xffffffffu, s, o);
    if (lane == 0) rowsum[row] = s;
}

// ---------------------------------------------------------------------------
// List build: per row-tile, compact nonzero col-tile indices (ascending).
// ---------------------------------------------------------------------------
__global__ void listbuild_kernel(const int* __restrict__ flag,
                                 int* __restrict__ list, int* __restrict__ cnt) {
    const int i = blockIdx.x, lane = threadIdx.x;
    unsigned b0 = __ballot_sync(0xffffffffu, flag[i * 64 + lane] != 0);
    unsigned b1 = __ballot_sync(0xffffffffu, flag[i * 64 + 32 + lane] != 0);
    if (lane == 0) {
        int c = 0;
        for (int j = 0; j < 32; j++) if ((b0 >> j) & 1) list[i * 64 + c++] = j;
        for (int j = 0; j < 32; j++) if ((b1 >> j) & 1) list[i * 64 + c++] = j + 32;
        cnt[i] = c;
    }
}

// ---------------------------------------------------------------------------
// Transposes: out[Cc][R] = in[R][Cc]
// ---------------------------------------------------------------------------
__global__ void transpose_f2h_kernel(const float* __restrict__ in, __half* __restrict__ out,
                                     int R, int Cc) {
    __shared__ float tile[32][34];
    const int bx = blockIdx.x * 32, by = blockIdx.y * 32;
    int x = bx + threadIdx.x;
    #pragma unroll
    for (int i = 0; i < 32; i += 8)
        tile[threadIdx.y + i][threadIdx.x] = in[(size_t)(by + threadIdx.y + i) * Cc + x];
    __syncthreads();
    x = by + threadIdx.x;
    #pragma unroll
    for (int i = 0; i < 32; i += 8)
        out[(size_t)(bx + threadIdx.y + i) * R + x] = __float2half(tile[threadIdx.x][threadIdx.y + i]);
}
__global__ void transpose_h2h_kernel(const __half* __restrict__ in, __half* __restrict__ out,
                                     int R, int Cc) {
    __shared__ __half tile[32][34];
    const int bx = blockIdx.x * 32, by = blockIdx.y * 32;
    int x = bx + threadIdx.x;
    #pragma unroll
    for (int i = 0; i < 32; i += 8)
        tile[threadIdx.y + i][threadIdx.x] = in[(size_t)(by + threadIdx.y + i) * Cc + x];
    __syncthreads();
    x = by + threadIdx.x;
    #pragma unroll
    for (int i = 0; i < 32; i += 8)
        out[(size_t)(bx + threadIdx.y + i) * R + x] = tile[threadIdx.x][threadIdx.y + i];
}

// ===========================================================================
// Shared GEMM mainloop: CTA 128x128, 4 warps (128 thr), warp grid 2x2,
// warp tile 64x64. K-chunk 64, 3-stage cp.async, XOR-swizzled smem,
// ldmatrix.x4 for A and B. 2 CTAs/SM.
// ===========================================================================
#define GEMM_DECLS()                                                                 \
    const uint32_t sA = smem_u32(smem);                                              \
    const uint32_t sB = sA + 3u * 16384u;                                            \
    const int tid  = threadIdx.x;                                                    \
    const int lane = tid & 31, wid = tid >> 5;                                       \
    const int wm = wid >> 1, wn = wid & 1;                                           \
    const int q  = lane & 3, gr = lane >> 2;                                         \
    float acc[4][8][4];                                                              \
    _Pragma("unroll") for (int i = 0; i < 4; i++)                                    \
        _Pragma("unroll") for (int j = 0; j < 8; j++)                                \
            _Pragma("unroll") for (int c = 0; c < 4; c++) acc[i][j][c] = 0.f;        \
    const int a_row_in = ((lane >> 3) & 1) * 8 + (lane & 7);                         \
    const int a_gsel   = lane >> 4;                                                  \
    const int b_nt_ofs = (lane >> 4);                                                \
    const int b_kh     = (lane >> 3) & 1;                                            \
    const int b_row_in = lane & 7;

#define GEMM_COMPUTE_CHUNK(stg)                                                      \
    {                                                                                \
        const uint32_t aB = sA + (uint32_t)(stg) * 16384u;                           \
        const uint32_t bB = sB + (uint32_t)(stg) * 16384u;                           \
        _Pragma("unroll") for (int ks = 0; ks < 4; ks++) {                           \
            uint32_t a[4][4];                                                        \
            _Pragma("unroll") for (int mt = 0; mt < 4; mt++) {                       \
                const int row = wm * 64 + mt * 16 + a_row_in;                        \
                const uint32_t g = (uint32_t)((2 * ks + a_gsel) ^ (row & 7));        \
                ldsm_x4(a[mt], aB + (uint32_t)(row * 128) + (g << 4));               \
            }                                                                        \
            _Pragma("unroll") for (int p = 0; p < 4; p++) {                          \
                uint32_t bfr[4];                                                     \
                const int n = wn * 64 + (2 * p + b_nt_ofs) * 8 + b_row_in;           \
                const uint32_t g = (uint32_t)((2 * ks + b_kh) ^ (n & 7));            \
                ldsm_x4(bfr, bB + (uint32_t)(n * 128) + (g << 4));                   \
                _Pragma("unroll") for (int mt = 0; mt < 4; mt++) {                   \
                    mma_f16(acc[mt][2 * p],     a[mt], bfr[0], bfr[1]);              \
                    mma_f16(acc[mt][2 * p + 1], a[mt], bfr[2], bfr[3]);              \
                }                                                                    \
            }                                                                        \
        }                                                                            \
    }

#define GEMM_LOAD_CHUNK_BODY(A_, B_, K_, bm_, bn_, k0, stg)                          \
    _Pragma("unroll") for (int i = 0; i < 8; i++) {                                  \
        int idx = tid + i * 128;                                                     \
        int r = idx >> 3, cg = idx & 7;                                              \
        uint32_t off = (uint32_t)(r * 128 + ((cg ^ (r & 7)) << 4));                  \
        cp16(sA + (uint32_t)(stg) * 16384u + off,                                    \
             (A_) + (size_t)((bm_) + r) * (K_) + (k0) + cg * 8);                     \
    }                                                                                \
    _Pragma("unroll") for (int i = 0; i < 8; i++) {                                  \
        int idx = tid + i * 128;                                                     \
        int r = idx >> 3, cg = idx & 7;                                              \
        uint32_t off = (uint32_t)(r * 128 + ((cg ^ (r & 7)) << 4));                  \
        cp16(sB + (uint32_t)(stg) * 16384u + off,                                    \
             (B_) + (size_t)((bn_) + r) * (K_) + (k0) + cg * 8);                     \
    }                                                                                \
    asm volatile("cp.async.commit_group;");

// ---------------------------------------------------------------------------
// Symmetric QK kernel, COMPACT 1-D triangular grid (2080 CTAs, bj >= bi).
// exp epilogue + partial row sums + nonzero-tile flags; mirror epilogue
// writes the (bj,bi) tile.
// ---------------------------------------------------------------------------
__global__ __launch_bounds__(128, 2)
void qk_gemm(const __half* __restrict__ A,
             __half* __restrict__ Sh, const float* __restrict__ sp,
             float* __restrict__ partial, int* __restrict__ flag, float scale) {
    // invert u -> (bi, bj): off(b) = 64b - b(b-1)/2
    const int u = blockIdx.x;
    int bi = (int)((129.0f - sqrtf(16641.0f - 8.0f * (float)u)) * 0.5f);
    while (64 * bi - (bi * (bi - 1)) / 2 > u) bi--;
    while (64 * (bi + 1) - ((bi + 1) * bi) / 2 <= u) bi++;
    const int bj = bi + (u - (64 * bi - (bi * (bi - 1)) / 2));
    const int bm = bi * 128, bn = bj * 128;

    extern __shared__ char smem[];
    __shared__ int warpany[4];

    GEMM_DECLS()
    auto load_chunk = [&](int k0, int stg) { GEMM_LOAD_CHUNK_BODY(A, A, EMB, bm, bn, k0, stg) };
    const int nk = EMB / 64;
    load_chunk(0, 0);
    load_chunk(64, 1);
    for (int kc = 0; kc < nk; kc++) {
        if (kc == nk - 1) asm volatile("cp.async.wait_group %0;" :: "n"(0));
        else              asm volatile("cp.async.wait_group %0;" :: "n"(1));
        __syncthreads();
        GEMM_COMPUTE_CHUNK(kc % 3)
        if (kc + 2 < nk) load_chunk((kc + 2) * 64, (kc + 2) % 3);
    }

    // ---- normal epilogue (upper tile) ----
    uint32_t uany = 0;
    #pragma unroll
    for (int mt = 0; mt < 4; mt++) {
        #pragma unroll
        for (int half_ = 0; half_ < 2; half_++) {
            const int r = bm + wm * 64 + mt * 16 + gr + half_ * 8;
            const size_t ro = (size_t)r * NROWS;
            float rsum0 = 0.f, rsum1 = 0.f;
            #pragma unroll
            for (int nt = 0; nt < 8; nt++) {
                const int c0 = bn + wn * 64 + nt * 8 + 2 * q;
                float v0 = acc[mt][nt][2 * half_ + 0];
                float v1 = acc[mt][nt][2 * half_ + 1];
                float2 a2 = *reinterpret_cast<const float2*>(sp + ro + c0);
                float e0 = __expf(v0 * scale + a2.x - EXP_SHIFT);
                float e1 = __expf(v1 * scale + a2.y - EXP_SHIFT);
                __half2 hh = __floats2half2_rn(e0, e1);
                *reinterpret_cast<__half2*>(Sh + ro + c0) = hh;
                uany |= reinterpret_cast<uint32_t&>(hh);
                if (nt < 4) rsum0 += e0 + e1; else rsum1 += e0 + e1;
            }
            rsum0 += __shfl_xor_sync(0xffffffffu, rsum0, 1);
            rsum0 += __shfl_xor_sync(0xffffffffu, rsum0, 2);
            rsum1 += __shfl_xor_sync(0xffffffffu, rsum1, 1);
            rsum1 += __shfl_xor_sync(0xffffffffu, rsum1, 2);
            if (q == 0) {
                partial[(size_t)r * 256 + (size_t)(bj * 4 + wn * 2 + 0)] = rsum0;
                partial[(size_t)r * 256 + (size_t)(bj * 4 + wn * 2 + 1)] = rsum1;
            }
        }
    }
    {
        int wa = __any_sync(0xffffffffu, uany != 0);
        if (lane == 0) warpany[wid] = wa;
        __syncthreads();
        if (tid == 0) {
            int f = warpany[0] | warpany[1] | warpany[2] | warpany[3];
            flag[bi * 64 + bj] = f;
        }
    }

    // ---- mirror epilogue (lower tile), bj > bi only ----
    if (bj > bi) {
        float* smT = reinterpret_cast<float*>(smem);   // 128 cols x stride 132 fp32
        __syncthreads();
        #pragma unroll
        for (int mt = 0; mt < 4; mt++) {
            #pragma unroll
            for (int half_ = 0; half_ < 2; half_++) {
                const int r = wm * 64 + mt * 16 + gr + half_ * 8;
                #pragma unroll
                for (int nt = 0; nt < 8; nt++) {
                    const int c = wn * 64 + nt * 8 + 2 * q;
                    smT[(size_t)c * 132 + r]       = acc[mt][nt][2 * half_ + 0];
                    smT[(size_t)(c + 1) * 132 + r] = acc[mt][nt][2 * half_ + 1];
                }
            }
        }
        __syncthreads();

        const int c = tid;                          // one col per thread
        const size_t orow = (size_t)(bn + c) * NROWS + bm;
        const float* srow = smT + (size_t)c * 132;
        const float* sprow = sp + orow;
        float s[4] = {0.f, 0.f, 0.f, 0.f};
        uint32_t uany2 = 0;
        #pragma unroll
        for (int i = 0; i < 128; i += 8) {
            float4 f0 = *reinterpret_cast<const float4*>(srow + i);
            float4 f1 = *reinterpret_cast<const float4*>(srow + i + 4);
            float4 p0 = *reinterpret_cast<const float4*>(sprow + i);
            float4 p1 = *reinterpret_cast<const float4*>(sprow + i + 4);
            float e0 = __expf(f0.x * scale + p0.x - EXP_SHIFT);
            float e1 = __expf(f0.y * scale + p0.y - EXP_SHIFT);
            float e2 = __expf(f0.z * scale + p0.z - EXP_SHIFT);
            float e3 = __expf(f0.w * scale + p0.w - EXP_SHIFT);
            float e4 = __expf(f1.x * scale + p1.x - EXP_SHIFT);
            float e5 = __expf(f1.y * scale + p1.y - EXP_SHIFT);
            float e6 = __expf(f1.z * scale + p1.z - EXP_SHIFT);
            float e7 = __expf(f1.w * scale + p1.w - EXP_SHIFT);
            float sum8 = ((e0 + e1) + (e2 + e3)) + ((e4 + e5) + (e6 + e7));
            s[i >> 5] += sum8;
            __half2 o[4];
            o[0] = __floats2half2_rn(e0, e1); o[1] = __floats2half2_rn(e2, e3);
            o[2] = __floats2half2_rn(e4, e5); o[3] = __floats2half2_rn(e6, e7);
            uint4 u4 = *reinterpret_cast<uint4*>(o);
            uany2 |= u4.x | u4.y | u4.z | u4.w;
            *reinterpret_cast<uint4*>(Sh + orow + i) = u4;
        }
        #pragma unroll
        for (int k = 0; k < 4; k++)
            partial[(size_t)(bn + c) * 256 + (size_t)((bm >> 5) + k)] = s[k];

        int wa2 = __any_sync(0xffffffffu, uany2 != 0);
        __syncthreads();
        if (lane == 0) warpany[wid] = wa2;
        __syncthreads();
        if (tid == 0) {
            int f = warpany[0] | warpany[1] | warpany[2] | warpany[3];
            flag[bj * 64 + bi] = f;
        }
    }
}

// ---------------------------------------------------------------------------
// AV GEMM with zero-tile skipping: iterates only k-chunks listed nonzero.
// x2 = acc / rowsum[r] + x
// ---------------------------------------------------------------------------
__global__ __launch_bounds__(128, 2)
void av_gemm(const __half* __restrict__ A, const __half* __restrict__ B,
             float* __restrict__ C, const float* __restrict__ xres,
             const float* __restrict__ rowsum,
             const int* __restrict__ list, const int* __restrict__ cnt) {
    extern __shared__ char smem[];
    __shared__ int slist[64];
    const int ti = blockIdx.y;
    const int bm = ti * 128, bn = blockIdx.x * 128;
    {
        const int t0 = threadIdx.x;
        if (t0 < 64) slist[t0] = list[ti * 64 + t0];
    }
    __syncthreads();
    const int nchunks = 2 * cnt[ti];

    GEMM_DECLS()
    auto load_chunk = [&](int ci, int stg) {
        const int k0 = slist[ci >> 1] * 128 + ((ci & 1) << 6);
        GEMM_LOAD_CHUNK_BODY(A, B, NROWS, bm, bn, k0, stg)
    };

    if (nchunks > 0) load_chunk(0, 0);
    if (nchunks > 1) load_chunk(1, 1);
    for (int ci = 0; ci < nchunks; ci++) {
        if (ci >= nchunks - 1) asm volatile("cp.async.wait_group %0;" :: "n"(0));
        else                   asm volatile("cp.async.wait_group %0;" :: "n"(1));
        __syncthreads();
        GEMM_COMPUTE_CHUNK(ci % 3)
        if (ci + 2 < nchunks) load_chunk(ci + 2, (ci + 2) % 3);
    }

    #pragma unroll
    for (int mt = 0; mt < 4; mt++) {
        #pragma unroll
        for (int half_ = 0; half_ < 2; half_++) {
            const int r = bm + wm * 64 + mt * 16 + gr + half_ * 8;
            const size_t ro = (size_t)r * EMB;
            const float inv = 1.0f / rowsum[r];
            #pragma unroll
            for (int nt = 0; nt < 8; nt++) {
                const int c0 = bn + wn * 64 + nt * 8 + 2 * q;
                float v0 = acc[mt][nt][2 * half_ + 0];
                float v1 = acc[mt][nt][2 * half_ + 1];
                float2 a2 = *reinterpret_cast<const float2*>(xres + ro + c0);
                *reinterpret_cast<float2*>(C + ro + c0) =
                    make_float2(v0 * inv + a2.x, v1 * inv + a2.y);
            }
        }
    }
}

// ---------------------------------------------------------------------------
// Generic GEMM (modes 2-3).
// MODE 2: C = half(relu(acc + bias))
// MODE 3: C = acc + bias + aux (f32)
// ---------------------------------------------------------------------------
template <int MODE>
__global__ __launch_bounds__(128, 2)
void mma_gemm(const __half* __restrict__ A, const __half* __restrict__ B,
              void* __restrict__ Cv, int M, int Nn, int K,
              const float* __restrict__ aux, const float* __restrict__ bias) {
    const int bm = blockIdx.y * 128, bn = blockIdx.x * 128;
    extern __shared__ char smem[];

    GEMM_DECLS()
    auto load_chunk = [&](int k0, int stg) { GEMM_LOAD_CHUNK_BODY(A, B, K, bm, bn, k0, stg) };
    const int nk = K / 64;
    load_chunk(0, 0);
    load_chunk(64, 1);
    for (int kc = 0; kc < nk; kc++) {
        if (kc == nk - 1) asm volatile("cp.async.wait_group %0;" :: "n"(0));
        else              asm volatile("cp.async.wait_group %0;" :: "n"(1));
        __syncthreads();
        GEMM_COMPUTE_CHUNK(kc % 3)
        if (kc + 2 < nk) load_chunk((kc + 2) * 64, (kc + 2) % 3);
    }

    #pragma unroll
    for (int mt = 0; mt < 4; mt++) {
        #pragma unroll
        for (int half_ = 0; half_ < 2; half_++) {
            const int r = bm + wm * 64 + mt * 16 + gr + half_ * 8;
            const size_t ro = (size_t)r * Nn;
            #pragma unroll
            for (int nt = 0; nt < 8; nt++) {
                const int c0 = bn + wn * 64 + nt * 8 + 2 * q;
                float v0 = acc[mt][nt][2 * half_ + 0];
                float v1 = acc[mt][nt][2 * half_ + 1];
                if (MODE == 2) {
                    float2 b2 = *reinterpret_cast<const float2*>(bias + c0);
                    *reinterpret_cast<__half2*>((__half*)Cv + ro + c0) =
                        __floats2half2_rn(fmaxf(v0 + b2.x, 0.f), fmaxf(v1 + b2.y, 0.f));
                } else {
                    float2 a2 = *reinterpret_cast<const float2*>(aux + ro + c0);
                    float2 b2 = *reinterpret_cast<const float2*>(bias + c0);
                    *reinterpret_cast<float2*>((float*)Cv + ro + c0) =
                        make_float2(v0 + b2.x + a2.x, v1 + b2.y + a2.y);
                }
            }
        }
    }
}

// ---------------------------------------------------------------------------
extern "C" void kernel_launch(void* const* d_in, const int* in_sizes, int n_in,
                              void* d_out, int out_size) {
    const float* x   = (const float*)d_in[0];
    const float* sp  = (const float*)d_in[2];
    const float* g1  = (const float*)d_in[3];
    const float* b1  = (const float*)d_in[4];
    const float* g2  = (const float*)d_in[5];
    const float* b2  = (const float*)d_in[6];
    const float* W1  = (const float*)d_in[7];
    const float* bb1 = (const float*)d_in[8];
    const float* W2  = (const float*)d_in[9];
    const float* bb2 = (const float*)d_in[10];
    float* out = (float*)d_out;

    __half *normx, *normxT, *Sh, *h, *t, *W1T, *W2T;
    float *x2, *partial, *rowsum;
    int *flag, *list, *cnt;
    cudaGetSymbolAddress((void**)&normx,   g_normx);
    cudaGetSymbolAddress((void**)&normxT,  g_normxT);
    cudaGetSymbolAddress((void**)&Sh,      g_Sh);
    cudaGetSymbolAddress((void**)&partial, g_partial);
    cudaGetSymbolAddress((void**)&rowsum,  g_rowsum);
    cudaGetSymbolAddress((void**)&flag,    g_flag);
    cudaGetSymbolAddress((void**)&list,    g_list);
    cudaGetSymbolAddress((void**)&cnt,     g_cnt);
    cudaGetSymbolAddress((void**)&x2,      g_x2);
    cudaGetSymbolAddress((void**)&h,       g_h);
    cudaGetSymbolAddress((void**)&t,       g_t);
    cudaGetSymbolAddress((void**)&W1T,     g_W1T);
    cudaGetSymbolAddress((void**)&W2T,     g_W2T);

    const int SMEM = 96 * 1024;
    cudaFuncSetAttribute(qk_gemm,     cudaFuncAttributeMaxDynamicSharedMemorySize, SMEM);
    cudaFuncSetAttribute(av_gemm,     cudaFuncAttributeMaxDynamicSharedMemorySize, SMEM);
    cudaFuncSetAttribute(mma_gemm<2>, cudaFuncAttributeMaxDynamicSharedMemorySize, SMEM);
    cudaFuncSetAttribute(mma_gemm<3>, cudaFuncAttributeMaxDynamicSharedMemorySize, SMEM);

    const float scale = 0.044194173824159216f;  // 1/sqrt(512)

    // 0-2: LN + normx^T (QK deps only) — puts qk_gemm at launch index 3
    layernorm_kernel<<<NROWS / 2, 128>>>(x, g1, b1, normx);                       // 0
    layernorm_kernel<<<NROWS / 2, 128>>>(x + (size_t)(NROWS / 2) * EMB, g1, b1,
                                         normx + (size_t)(NROWS / 2) * EMB);      // 1
    transpose_h2h_kernel<<<dim3(EMB / 32, NROWS / 32), dim3(32, 8)>>>(
        normx, normxT, NROWS, EMB);                                               // 2

    // 3: symmetric QK, compact triangular grid (2080 CTAs)
    qk_gemm<<<NTRI, 128, SMEM>>>(normx, Sh, sp, partial, flag, scale);            // 3

    // 4-5: weight transposes (independent; overlap QK tail)
    transpose_f2h_kernel<<<dim3(DFF / 32, EMB / 32), dim3(32, 8)>>>(W1, W1T, EMB, DFF);  // 4
    transpose_f2h_kernel<<<dim3(EMB / 32, DFF / 32), dim3(32, 8)>>>(W2, W2T, DFF, EMB);  // 5

    // 6: rowsum = sum of partials
    rowsum_kernel<<<NROWS / 8, 256>>>(partial, rowsum);                           // 6

    // 7: compact nonzero col-tile lists
    listbuild_kernel<<<NT64, 32>>>(flag, list, cnt);                              // 7

    // 8: x2 = (expS @ norm_x) / rowsum + x, skipping all-zero Sh tiles
    av_gemm<<<dim3(EMB / 128, NROWS / 128), 128, SMEM>>>(
        Sh, normxT, x2, x, rowsum, list, cnt);                                    // 8

    // 9: h = LN(x2; g2, b2) -> half
    layernorm_kernel<<<NROWS, 128>>>(x2, g2, b2, h);                              // 9

    // 10: t = relu(h @ W1 + bb1) -> half
    mma_gemm<2><<<dim3(DFF / 128, NROWS / 128), 128, SMEM>>>(
        h, W1T, t, NROWS, DFF, EMB, nullptr, bb1);                                // 10

    // 11: out = t @ W2 + bb2 + x2
    mma_gemm<3><<<dim3(EMB / 128, NROWS / 128), 128, SMEM>>>(
        t, W2T, out, NROWS, EMB, DFF, x2, bb2);                                   // 11
}